// round 12
// baseline (speedup 1.0000x reference)
#include <cuda_runtime.h>
#include <cuda_fp16.h>
#include <math.h>
#include <stdint.h>

#define BB 128
#define NN 512
#define KNN 16
#define E_TOT (BB*NN*KNN)      /* 1048576 edges */
#define NTILES (E_TOT/64)      /* 16384 tiles of 64 edges */
#define L1GRID 296
#define L2GRID 148
#define SGRID 512

typedef unsigned long long u64;

// ---------------- packed f32x2 helpers ----------------
__device__ __forceinline__ u64 pack2(float lo, float hi) {
    u64 r; asm("mov.b64 %0, {%1,%2};" : "=l"(r) : "f"(lo), "f"(hi)); return r;
}
__device__ __forceinline__ float2 unpack2(u64 v) {
    float2 r; asm("mov.b64 {%0,%1}, %2;" : "=f"(r.x), "=f"(r.y) : "l"(v)); return r;
}
__device__ __forceinline__ u64 fma2(u64 a, u64 b, u64 c) {
    u64 d; asm("fma.rn.f32x2 %0, %1, %2, %3;" : "=l"(d) : "l"(a), "l"(b), "l"(c)); return d;
}
__device__ __forceinline__ u64 add2(u64 a, u64 b) {
    u64 d; asm("add.rn.f32x2 %0, %1, %2;" : "=l"(d) : "l"(a), "l"(b)); return d;
}
__device__ __forceinline__ u64 lds_b64(unsigned int saddr) {
    u64 d; asm("ld.shared.b64 %0, [%1];" : "=l"(d) : "r"(saddr)); return d;
}
__device__ __forceinline__ void lds_v2b64(unsigned int saddr, u64& a, u64& b) {
    asm("ld.shared.v2.b64 {%0,%1}, [%2];" : "=l"(a), "=l"(b) : "r"(saddr));
}
__device__ __forceinline__ void sts_b64(unsigned int saddr, u64 v) {
    asm volatile("st.shared.b64 [%0], %1;" :: "r"(saddr), "l"(v));
}
__device__ __forceinline__ uint32_t smem_u32(const void* p) {
    uint32_t a;
    asm("{ .reg .u64 t; cvta.to.shared.u64 t, %1; cvt.u32.u64 %0, t; }" : "=r"(a) : "l"(p));
    return a;
}
__device__ __forceinline__ uint32_t h2bits(__half2 h) {
    return *reinterpret_cast<uint32_t*>(&h);
}

// ---------------- scratch (static __device__; no allocation) ----------------
__device__ int   g_idx[E_TOT];
__device__ float g_PQS[BB*NN*256];          // [p][0:64)=P, [64:128)=Q, [128:256)=sc pre-BN
__device__ float g_Wcat[256*64];
__device__ float g_W1t[64*128];             // [c][r]
__device__ float g_W2t[128*128];            // [c][r]
__device__ __half g_y1h[134217728];         // [t][128ch][64e] pre-BN layer1 (fp16)
__device__ __half g_y2h[134217728];         // [t][128ch][64e] pre-BN layer2 (fp16)
__device__ float g_part0[SGRID*128];
__device__ float g_partsc[SGRID*256];
__device__ float g_part1[2048*256];
__device__ float g_part2[2048*256];
__device__ float g_a0[64],  g_c0[64];
__device__ float g_a1[128], g_c1[128];
__device__ float g_a2[128], g_c2[128];
__device__ float g_asc[128], g_csc[128];

// ---------------- prep ----------------
__global__ void prep_kernel(const float* __restrict__ w0, const float* __restrict__ w1,
                            const float* __restrict__ w2, const float* __restrict__ scw) {
    int tid = threadIdx.x;
    for (int i = tid; i < 64*64; i += 256) {
        int r = i >> 6, c = i & 63;
        g_Wcat[r*64 + c] = w0[r*128 + c] - w0[r*128 + 64 + c];
    }
    for (int i = tid; i < 64*64; i += 256) {
        int r = i >> 6, c = i & 63;
        g_Wcat[(64 + r)*64 + c] = w0[r*128 + 64 + c];
    }
    for (int i = tid; i < 128*64; i += 256) {
        int r = i >> 6, c = i & 63;
        g_Wcat[(128 + r)*64 + c] = scw[r*64 + c];
    }
    for (int i = tid; i < 128*64; i += 256) {
        int r = i & 127, c = i >> 7;
        g_W1t[c*128 + r] = w1[r*64 + c];
    }
    for (int i = tid; i < 128*128; i += 256) {
        int r = i & 127, c = i >> 7;
        g_W2t[c*128 + r] = w2[r*128 + c];
    }
}

// ---------------- kNN ----------------
__global__ void knn_kernel(const float* __restrict__ pts) {
    __shared__ float px[512], py[512];
    int b = blockIdx.x, n = threadIdx.x;
    px[n] = pts[b*1024 + n];
    py[n] = pts[b*1024 + 512 + n];
    __syncthreads();
    float x0 = px[n], y0v = py[n];
    float bd[KNN]; int bi[KNN];
#pragma unroll
    for (int i = 0; i < KNN; i++) { bd[i] = 1e30f; bi[i] = 0; }
    for (int m = 0; m < 512; m++) {
        if (m == n) continue;
        float dx = px[m] - x0, dy = py[m] - y0v;
        float d = fmaf(dx, dx, dy*dy);
        if (d < bd[KNN-1]) {
            int j = KNN - 1;
            while (j > 0 && bd[j-1] > d) { bd[j] = bd[j-1]; bi[j] = bi[j-1]; j--; }
            bd[j] = d; bi[j] = m;
        }
    }
    int base = (b*512 + n)*KNN;
#pragma unroll
    for (int k = 0; k < KNN; k++) g_idx[base + k] = bi[k];
}

// ---------------- gemm_f ----------------
__global__ void gemm_f_kernel(const float* __restrict__ f) {
    __shared__ float Wst[64*65];
    __shared__ float fs[64*65];
    int tid = threadIdx.x;
    int rt0 = blockIdx.x*64, n0 = blockIdx.y*64, b = blockIdx.z;
#pragma unroll
    for (int s = 0; s < 16; s++) {
        int idx = tid + 256*s;
        int c = idx & 63, rl = idx >> 6;
        Wst[c*65 + rl] = g_Wcat[(rt0 + rl)*64 + c];
    }
#pragma unroll
    for (int s = 0; s < 16; s++) {
        int idx = tid + 256*s;
        int nl = idx & 63, c = idx >> 6;
        fs[c*65 + nl] = f[b*32768 + c*512 + n0 + nl];
    }
    __syncthreads();
    int tx = tid & 15, ty = tid >> 4;
    float acc[4][4];
#pragma unroll
    for (int i = 0; i < 4; i++)
#pragma unroll
        for (int j = 0; j < 4; j++) acc[i][j] = 0.f;
#pragma unroll 4
    for (int c = 0; c < 64; c++) {
        float fv[4];
#pragma unroll
        for (int j = 0; j < 4; j++) fv[j] = fs[c*65 + ty*4 + j];
#pragma unroll
        for (int i = 0; i < 4; i++) {
            float w = Wst[c*65 + tx + 16*i];
#pragma unroll
            for (int j = 0; j < 4; j++) acc[i][j] = fmaf(w, fv[j], acc[i][j]);
        }
    }
#pragma unroll
    for (int j = 0; j < 4; j++) {
        float* dst = &g_PQS[(size_t)(b*512 + n0 + ty*4 + j)*256 + rt0 + tx];
#pragma unroll
        for (int i = 0; i < 4; i++) dst[16*i] = acc[i][j];
    }
}

// ---------------- stats of y0 ----------------
__global__ void stats0_kernel() {
    __shared__ float red[128];
    int tid = threadIdx.x;
    int c = tid & 63, q = tid >> 6;
    float s = 0.f, s2 = 0.f;
    for (int p = blockIdx.x*4 + q; p < BB*NN; p += SGRID*4) {
        float Pv = g_PQS[(size_t)p*256 + c];
        size_t rowbase = (size_t)(p & ~511)*256;
#pragma unroll
        for (int k = 0; k < KNN; k++) {
            int m = g_idx[p*KNN + k];
            float y = Pv + g_PQS[rowbase + (size_t)m*256 + 64 + c];
            s += y; s2 += y*y;
        }
    }
    if (tid < 128) red[tid] = 0.f;
    __syncthreads();
    atomicAdd(&red[c], s);
    atomicAdd(&red[64 + c], s2);
    __syncthreads();
    if (tid < 128) g_part0[blockIdx.x*128 + tid] = red[tid];
}

// ---------------- stats of shortcut ----------------
__global__ void statssc_kernel() {
    __shared__ float red[256];
    int tid = threadIdx.x;
    int c = tid & 127, q = tid >> 7;
    float s = 0.f, s2 = 0.f;
    for (int p = blockIdx.x*2 + q; p < BB*NN; p += SGRID*2) {
        float v = g_PQS[(size_t)p*256 + 128 + c];
        s += v; s2 += v*v;
    }
    red[tid] = 0.f;
    __syncthreads();
    atomicAdd(&red[c], s);
    atomicAdd(&red[128 + c], s2);
    __syncthreads();
    g_partsc[blockIdx.x*256 + tid] = red[tid];
}

// ---------------- finalize ----------------
__global__ void finalize_kernel(const float* __restrict__ part, int nblocks, int nch,
                                const float* __restrict__ g, const float* __restrict__ bt,
                                float minv, float* a_out, float* c_out) {
    int c = threadIdx.x;
    if (c >= nch) return;
    float s = 0.f, s2 = 0.f;
    for (int i = 0; i < nblocks; i++) {
        s  += part[i*2*nch + c];
        s2 += part[i*2*nch + nch + c];
    }
    float mean = s*minv;
    float var = s2*minv - mean*mean;
    float a = g[c] * rsqrtf(var + 1e-5f);
    a_out[c] = a;
    c_out[c] = bt[c] - a*mean;
}

// x row stride: 65 u64 = 520B (bank-spread for fill STS and gemm LDS)
#define XROW 520u

// ---------------- layer1: FFMA2, 8r x 4e thread tiles, double-buffered x ----------------
// smem: W[64c][128r] fp32 32KB | xbuf0 [64c][65]u64 33280B | xbuf1 33280B
__global__ void __launch_bounds__(256, 2) layer1_kernel() {
    extern __shared__ char sm[];
    float* Wsm = (float*)sm;
    char* x0p = sm + 32768;
    char* x1p = sm + 32768 + 33280;
    __shared__ float sstat[256];
    int tid = threadIdx.x;
    {
        float4* d = (float4*)Wsm; const float4* s = (const float4*)g_W1t;
        for (int i = tid; i < 2048; i += 256) d[i] = s[i];
    }
    sstat[tid] = 0.f;

    // fill mapping: fixed channel c, 16 edges
    int c = tid & 63, eg = tid >> 6;
    float a0v = g_a0[c], c0v = g_c0[c];
    // gemm mapping: 8 rows x 4 edges
    int lane = tid & 31, wp = tid >> 5;
    int rb = wp & 3, eb = wp >> 2;
    int rg = lane >> 3, egg = lane & 7;
    int r0 = rb*32 + rg*8;
    int e0 = eb*32 + egg*4;
    uint32_t wbase = smem_u32(Wsm) + (uint32_t)r0*4u;
    uint32_t x0b = smem_u32(x0p), x1b = smem_u32(x1p);
    uint32_t xsts0 = x0b + (uint32_t)c*XROW;
    uint32_t xsts1 = x1b + (uint32_t)c*XROW;

    u64 rs[4], rqs[4];
#pragma unroll
    for (int i = 0; i < 4; i++) { rs[i] = 0ull; rqs[i] = 0ull; }

    int t = blockIdx.x;
    int mi[16]; float pv[16], qv[16];
    {
        int eb0 = t*64;
#pragma unroll
        for (int s = 0; s < 16; s++) mi[s] = g_idx[eb0 + eg*16 + s];
#pragma unroll
        for (int s = 0; s < 16; s++) { int p = (eb0 + eg*16 + s) >> 4; pv[s] = g_PQS[(size_t)p*256 + c]; }
#pragma unroll
        for (int s = 0; s < 16; s++) {
            int p = (eb0 + eg*16 + s) >> 4;
            qv[s] = g_PQS[(size_t)((p & ~511) + mi[s])*256 + 64 + c];
        }
    }
    __syncthreads();

    int par = 0;
    for (; t < NTILES; t += L1GRID) {
        uint32_t xs = par ? xsts1 : xsts0;
#pragma unroll
        for (int s = 0; s < 16; s++) {
            float v = fmaxf(fmaf(a0v, pv[s] + qv[s], c0v), 0.f);
            sts_b64(xs + (uint32_t)(eg*16 + s)*8u, pack2(v, v));
        }
        __syncthreads();
        int tn = t + L1GRID;
        if (tn < NTILES) {
            int eb0 = tn*64;
#pragma unroll
            for (int s = 0; s < 16; s++) mi[s] = g_idx[eb0 + eg*16 + s];
#pragma unroll
            for (int s = 0; s < 16; s++) { int p = (eb0 + eg*16 + s) >> 4; pv[s] = g_PQS[(size_t)p*256 + c]; }
        }
        u64 acc[4][4];
#pragma unroll
        for (int i = 0; i < 4; i++)
#pragma unroll
            for (int j = 0; j < 4; j++) acc[i][j] = 0ull;
        uint32_t wa = wbase;
        uint32_t xa = (par ? x1b : x0b) + (uint32_t)e0*8u;
#pragma unroll 8
        for (int cc = 0; cc < 64; cc++) {
            u64 wv0, wv1, wv2, wv3;
            lds_v2b64(wa, wv0, wv1);
            lds_v2b64(wa + 16u, wv2, wv3);
            u64 x0 = lds_b64(xa), x1 = lds_b64(xa + 8u), x2 = lds_b64(xa + 16u), x3 = lds_b64(xa + 24u);
            acc[0][0] = fma2(wv0, x0, acc[0][0]); acc[0][1] = fma2(wv0, x1, acc[0][1]);
            acc[0][2] = fma2(wv0, x2, acc[0][2]); acc[0][3] = fma2(wv0, x3, acc[0][3]);
            acc[1][0] = fma2(wv1, x0, acc[1][0]); acc[1][1] = fma2(wv1, x1, acc[1][1]);
            acc[1][2] = fma2(wv1, x2, acc[1][2]); acc[1][3] = fma2(wv1, x3, acc[1][3]);
            acc[2][0] = fma2(wv2, x0, acc[2][0]); acc[2][1] = fma2(wv2, x1, acc[2][1]);
            acc[2][2] = fma2(wv2, x2, acc[2][2]); acc[2][3] = fma2(wv2, x3, acc[2][3]);
            acc[3][0] = fma2(wv3, x0, acc[3][0]); acc[3][1] = fma2(wv3, x1, acc[3][1]);
            acc[3][2] = fma2(wv3, x2, acc[3][2]); acc[3][3] = fma2(wv3, x3, acc[3][3]);
            wa += 512u; xa += XROW;
        }
        if (tn < NTILES) {
            int eb0 = tn*64;
#pragma unroll
            for (int s = 0; s < 16; s++) {
                int p = (eb0 + eg*16 + s) >> 4;
                qv[s] = g_PQS[(size_t)((p & ~511) + mi[s])*256 + 64 + c];
            }
        }
#pragma unroll
        for (int i = 0; i < 4; i++) {
#pragma unroll
            for (int j = 0; j < 4; j++) {
                rs[i] = add2(rs[i], acc[i][j]);
                rqs[i] = fma2(acc[i][j], acc[i][j], rqs[i]);
            }
            float2 f0 = unpack2(acc[i][0]), f1 = unpack2(acc[i][1]);
            float2 f2 = unpack2(acc[i][2]), f3 = unpack2(acc[i][3]);
            size_t ro = ((size_t)t*128 + r0 + 2*i)*64 + e0;
            uint2 lo, hi;
            lo.x = h2bits(__floats2half2_rn(f0.x, f1.x)); lo.y = h2bits(__floats2half2_rn(f2.x, f3.x));
            hi.x = h2bits(__floats2half2_rn(f0.y, f1.y)); hi.y = h2bits(__floats2half2_rn(f2.y, f3.y));
            *(uint2*)&g_y1h[ro]      = lo;
            *(uint2*)&g_y1h[ro + 64] = hi;
        }
        par ^= 1;
    }
#pragma unroll
    for (int i = 0; i < 4; i++) {
        float2 s2 = unpack2(rs[i]), q2 = unpack2(rqs[i]);
#pragma unroll
        for (int off = 1; off < 8; off <<= 1) {
            s2.x += __shfl_xor_sync(0xffffffffu, s2.x, off);
            s2.y += __shfl_xor_sync(0xffffffffu, s2.y, off);
            q2.x += __shfl_xor_sync(0xffffffffu, q2.x, off);
            q2.y += __shfl_xor_sync(0xffffffffu, q2.y, off);
        }
        if (egg == 0) {
            atomicAdd(&sstat[r0 + 2*i],         s2.x);
            atomicAdd(&sstat[r0 + 2*i + 1],     s2.y);
            atomicAdd(&sstat[128 + r0 + 2*i],   q2.x);
            atomicAdd(&sstat[128 + r0 + 2*i+1], q2.y);
        }
    }
    __syncthreads();
    g_part1[blockIdx.x*256 + tid] = sstat[tid];
}

// ---------------- layer2: FFMA2, 8r x 4e, K=128, single x buffer ----------------
// smem: W[128c][128r] fp32 64KB | xbuf [128c][65]u64 66560B
__global__ void __launch_bounds__(256) layer2_kernel() {
    extern __shared__ char sm[];
    float* Wsm = (float*)sm;
    char* xp = sm + 65536;
    __shared__ float sstat[256];
    __shared__ float s_a[128], s_c[128];
    int tid = threadIdx.x;
    {
        float4* d = (float4*)Wsm; const float4* s = (const float4*)g_W2t;
        for (int i = tid; i < 4096; i += 256) d[i] = s[i];
    }
    if (tid < 128) { s_a[tid] = g_a1[tid]; s_c[tid] = g_c1[tid]; }
    sstat[tid] = 0.f;

    int k0 = tid >> 5, e2 = tid & 31;     // fill mapping: half2 columns
    int lane = tid & 31, wp = tid >> 5;
    int rb = wp & 3, eb = wp >> 2;
    int rg = lane >> 3, egg = lane & 7;
    int r0 = rb*32 + rg*8;
    int e0 = eb*32 + egg*4;
    uint32_t wbase = smem_u32(Wsm) + (uint32_t)r0*4u;
    uint32_t xb = smem_u32(xp);
    uint32_t xgb = xb + (uint32_t)e0*8u;

    u64 rs[4], rqs[4];
#pragma unroll
    for (int i = 0; i < 4; i++) { rs[i] = 0ull; rqs[i] = 0ull; }

    const uint32_t* y1p = (const uint32_t*)g_y1h;
    int t = blockIdx.x;
    uint32_t h[16];
    {
#pragma unroll
        for (int s = 0; s < 16; s++)
            h[s] = y1p[((size_t)t*128 + k0 + 8*s)*32 + e2];
    }
    __syncthreads();

    for (; t < NTILES; t += L2GRID) {
#pragma unroll
        for (int s = 0; s < 16; s++) {
            int k = k0 + 8*s;
            __half2 hh = *reinterpret_cast<__half2*>(&h[s]);
            float2 f = __half22float2(hh);
            float ak = s_a[k], ck = s_c[k];
            float v0 = fmaxf(fmaf(ak, f.x, ck), 0.f);
            float v1 = fmaxf(fmaf(ak, f.y, ck), 0.f);
            uint32_t sa = xb + (uint32_t)k*XROW + (uint32_t)e2*16u;
            sts_b64(sa,      pack2(v0, v0));
            sts_b64(sa + 8u, pack2(v1, v1));
        }
        __syncthreads();
        int tn = t + L2GRID;
        if (tn < NTILES) {
#pragma unroll
            for (int s = 0; s < 16; s++)
                h[s] = y1p[((size_t)tn*128 + k0 + 8*s)*32 + e2];
        }
        u64 acc[4][4];
#pragma unroll
        for (int i = 0; i < 4; i++)
#pragma unroll
            for (int j = 0; j < 4; j++) acc[i][j] = 0ull;
        uint32_t wa = wbase, xa = xgb;
#pragma unroll 8
        for (int cc = 0; cc < 128; cc++) {
            u64 wv0, wv1, wv2, wv3;
            lds_v2b64(wa, wv0, wv1);
            lds_v2b64(wa + 16u, wv2, wv3);
            u64 x0 = lds_b64(xa), x1 = lds_b64(xa + 8u), x2 = lds_b64(xa + 16u), x3 = lds_b64(xa + 24u);
            acc[0][0] = fma2(wv0, x0, acc[0][0]); acc[0][1] = fma2(wv0, x1, acc[0][1]);
            acc[0][2] = fma2(wv0, x2, acc[0][2]); acc[0][3] = fma2(wv0, x3, acc[0][3]);
            acc[1][0] = fma2(wv1, x0, acc[1][0]); acc[1][1] = fma2(wv1, x1, acc[1][1]);
            acc[1][2] = fma2(wv1, x2, acc[1][2]); acc[1][3] = fma2(wv1, x3, acc[1][3]);
            acc[2][0] = fma2(wv2, x0, acc[2][0]); acc[2][1] = fma2(wv2, x1, acc[2][1]);
            acc[2][2] = fma2(wv2, x2, acc[2][2]); acc[2][3] = fma2(wv2, x3, acc[2][3]);
            acc[3][0] = fma2(wv3, x0, acc[3][0]); acc[3][1] = fma2(wv3, x1, acc[3][1]);
            acc[3][2] = fma2(wv3, x2, acc[3][2]); acc[3][3] = fma2(wv3, x3, acc[3][3]);
            wa += 512u; xa += XROW;
        }
#pragma unroll
        for (int i = 0; i < 4; i++) {
#pragma unroll
            for (int j = 0; j < 4; j++) {
                rs[i] = add2(rs[i], acc[i][j]);
                rqs[i] = fma2(acc[i][j], acc[i][j], rqs[i]);
            }
            float2 f0 = unpack2(acc[i][0]), f1 = unpack2(acc[i][1]);
            float2 f2 = unpack2(acc[i][2]), f3 = unpack2(acc[i][3]);
            size_t ro = ((size_t)t*128 + r0 + 2*i)*64 + e0;
            uint2 lo, hi;
            lo.x = h2bits(__floats2half2_rn(f0.x, f1.x)); lo.y = h2bits(__floats2half2_rn(f2.x, f3.x));
            hi.x = h2bits(__floats2half2_rn(f0.y, f1.y)); hi.y = h2bits(__floats2half2_rn(f2.y, f3.y));
            *(uint2*)&g_y2h[ro]      = lo;
            *(uint2*)&g_y2h[ro + 64] = hi;
        }
        __syncthreads();
    }
#pragma unroll
    for (int i = 0; i < 4; i++) {
        float2 s2 = unpack2(rs[i]), q2 = unpack2(rqs[i]);
#pragma unroll
        for (int off = 1; off < 8; off <<= 1) {
            s2.x += __shfl_xor_sync(0xffffffffu, s2.x, off);
            s2.y += __shfl_xor_sync(0xffffffffu, s2.y, off);
            q2.x += __shfl_xor_sync(0xffffffffu, q2.x, off);
            q2.y += __shfl_xor_sync(0xffffffffu, q2.y, off);
        }
        if (egg == 0) {
            atomicAdd(&sstat[r0 + 2*i],         s2.x);
            atomicAdd(&sstat[r0 + 2*i + 1],     s2.y);
            atomicAdd(&sstat[128 + r0 + 2*i],   q2.x);
            atomicAdd(&sstat[128 + r0 + 2*i+1], q2.y);
        }
    }
    __syncthreads();
    g_part2[blockIdx.x*256 + tid] = sstat[tid];
}

// ---------------- out ----------------
__global__ void out_kernel(float* __restrict__ out) {
    __shared__ float res[128*33];
    int tid = threadIdx.x;
    int b = blockIdx.x >> 4;
    int n0 = (blockIdx.x & 15)*32;
    int o = tid & 127, ng = tid >> 7;
    float a2v = g_a2[o], c2v = g_c2[o];
    float ascv = g_asc[o], cscv = g_csc[o];
#pragma unroll
    for (int s = 0; s < 16; s++) {
        int nloc = ng + 2*s;
        int p = b*512 + n0 + nloc;
        int t = p >> 2, q = p & 3;
        const __half2* yr = (const __half2*)&g_y2h[((size_t)t*128 + o)*64 + q*16];
        float fts = 0.f;
#pragma unroll
        for (int kk = 0; kk < 8; kk++) {
            float2 f = __half22float2(yr[kk]);
            fts += fmaxf(fmaf(a2v, f.x, c2v), 0.f) + fmaxf(fmaf(a2v, f.y, c2v), 0.f);
        }
        fts *= (1.0f/KNN);
        float sc = fmaf(ascv, g_PQS[(size_t)p*256 + 128 + o], cscv);
        res[o*33 + nloc] = fmaxf(sc + fts, 0.f);
    }
    __syncthreads();
#pragma unroll
    for (int s = 0; s < 16; s++) {
        int idx = tid + 256*s;
        int oo = idx >> 5, nl = idx & 31;
        out[(size_t)(b*128 + oo)*512 + n0 + nl] = res[oo*33 + nl];
    }
}

// ---------------- launch ----------------
extern "C" void kernel_launch(void* const* d_in, const int* in_sizes, int n_in,
                              void* d_out, int out_size) {
    const float* pts  = (const float*)d_in[0];
    const float* feat = (const float*)d_in[1];
    const float* w0   = (const float*)d_in[2];
    const float* g0   = (const float*)d_in[3];
    const float* b0   = (const float*)d_in[4];
    const float* w1   = (const float*)d_in[5];
    const float* g1   = (const float*)d_in[6];
    const float* b1   = (const float*)d_in[7];
    const float* w2   = (const float*)d_in[8];
    const float* g2   = (const float*)d_in[9];
    const float* b2   = (const float*)d_in[10];
    const float* scw  = (const float*)d_in[11];
    const float* scg  = (const float*)d_in[12];
    const float* scb  = (const float*)d_in[13];
    float* out = (float*)d_out;

    const int SMEM1 = 32768 + 2*33280;   // 99328
    const int SMEM2 = 65536 + 66560;     // 132096
    cudaFuncSetAttribute(layer1_kernel, cudaFuncAttributeMaxDynamicSharedMemorySize, SMEM1);
    cudaFuncSetAttribute(layer2_kernel, cudaFuncAttributeMaxDynamicSharedMemorySize, SMEM2);

    float *pa0, *pc0, *pa1, *pc1, *pa2, *pc2, *pasc, *pcsc;
    float *pp0, *ppsc, *pp1, *pp2;
    cudaGetSymbolAddress((void**)&pa0,  g_a0);
    cudaGetSymbolAddress((void**)&pc0,  g_c0);
    cudaGetSymbolAddress((void**)&pa1,  g_a1);
    cudaGetSymbolAddress((void**)&pc1,  g_c1);
    cudaGetSymbolAddress((void**)&pa2,  g_a2);
    cudaGetSymbolAddress((void**)&pc2,  g_c2);
    cudaGetSymbolAddress((void**)&pasc, g_asc);
    cudaGetSymbolAddress((void**)&pcsc, g_csc);
    cudaGetSymbolAddress((void**)&pp0,  g_part0);
    cudaGetSymbolAddress((void**)&ppsc, g_partsc);
    cudaGetSymbolAddress((void**)&pp1,  g_part1);
    cudaGetSymbolAddress((void**)&pp2,  g_part2);

    prep_kernel<<<1, 256>>>(w0, w1, w2, scw);
    knn_kernel<<<BB, 512>>>(pts);
    gemm_f_kernel<<<dim3(4, 8, BB), 256>>>(feat);
    stats0_kernel<<<SGRID, 256>>>();
    statssc_kernel<<<SGRID, 256>>>();
    finalize_kernel<<<1, 64>>>(pp0, SGRID, 64, g0, b0, 1.0f/(float)E_TOT, pa0, pc0);
    finalize_kernel<<<1, 128>>>(ppsc, SGRID, 128, scg, scb, 1.0f/(float)(BB*NN), pasc, pcsc);
    layer1_kernel<<<L1GRID, 256, SMEM1>>>();
    finalize_kernel<<<1, 128>>>(pp1, L1GRID, 128, g1, b1, 1.0f/(float)E_TOT, pa1, pc1);
    layer2_kernel<<<L2GRID, 256, SMEM2>>>();
    finalize_kernel<<<1, 128>>>(pp2, L2GRID, 128, g2, b2, 1.0f/(float)E_TOT, pa2, pc2);
    out_kernel<<<BB*16, 256>>>(out);

    (void)in_sizes; (void)n_in; (void)out_size;
}

// round 13
// speedup vs baseline: 1.3677x; 1.3677x over previous
#include <cuda_runtime.h>
#include <cuda_fp16.h>
#include <math.h>
#include <stdint.h>

#define BB 128
#define NN 512
#define KNN 16
#define E_TOT (BB*NN*KNN)      /* 1048576 edges */
#define NTILES (E_TOT/64)      /* 16384 tiles of 64 edges */
#define L1GRID 592
#define L2GRID 296
#define SGRID 512

// ---------------- helpers ----------------
__device__ __forceinline__ uint32_t smem_u32(const void* p) {
    uint32_t a;
    asm("{ .reg .u64 t; cvta.to.shared.u64 t, %1; cvt.u32.u64 %0, t; }" : "=r"(a) : "l"(p));
    return a;
}
#define LDSM_X4(r, a) \
    asm volatile("ldmatrix.sync.aligned.m8n8.x4.shared.b16 {%0,%1,%2,%3}, [%4];" \
        : "=r"((r)[0]), "=r"((r)[1]), "=r"((r)[2]), "=r"((r)[3]) : "r"(a))
#define LDSM_X2T(r, a) \
    asm volatile("ldmatrix.sync.aligned.m8n8.x2.trans.shared.b16 {%0,%1}, [%2];" \
        : "=r"((r)[0]), "=r"((r)[1]) : "r"(a))
#define MMA_F16(c, a, b) \
    asm volatile("mma.sync.aligned.m16n8k16.row.col.f32.f16.f16.f32 " \
        "{%0,%1,%2,%3}, {%4,%5,%6,%7}, {%8,%9}, {%0,%1,%2,%3};" \
        : "+f"((c)[0]), "+f"((c)[1]), "+f"((c)[2]), "+f"((c)[3]) \
        : "r"((a)[0]), "r"((a)[1]), "r"((a)[2]), "r"((a)[3]), "r"((b)[0]), "r"((b)[1]))

// ---------------- scratch (static __device__; no allocation) ----------------
__device__ int   g_idx[E_TOT];
__device__ float g_PQS[BB*NN*256];          // [p][0:64)=P, [64:128)=Q, [128:256)=sc pre-BN
__device__ float g_Wcat[256*64];
__device__ __align__(16) unsigned short g_w1h[128*72],  g_w1l[128*72];    // W1 fp16 hi/lo, stride 72
__device__ __align__(16) unsigned short g_w2h[128*136], g_w2l[128*136];   // W2 fp16 hi/lo, stride 136
__device__ __half g_y1h[134217728];         // [t][128ch][64e] pre-BN layer1 (fp16)
__device__ __half g_y2h[134217728];         // [t][128ch][64e] pre-BN layer2 (fp16)
__device__ float g_part0[SGRID*128];
__device__ float g_partsc[SGRID*256];
__device__ float g_part1[2048*256];
__device__ float g_part2[2048*256];
__device__ float g_a0[64],  g_c0[64];
__device__ float g_a1[128], g_c1[128];
__device__ float g_a2[128], g_c2[128];
__device__ float g_asc[128], g_csc[128];

// ---------------- prep: fold w0, split w1/w2 into fp16 hi/lo padded ----------------
__global__ void prep_kernel(const float* __restrict__ w0, const float* __restrict__ w1,
                            const float* __restrict__ w2, const float* __restrict__ scw) {
    int tid = threadIdx.x;
    for (int i = tid; i < 64*64; i += 256) {
        int r = i >> 6, c = i & 63;
        g_Wcat[r*64 + c] = w0[r*128 + c] - w0[r*128 + 64 + c];
    }
    for (int i = tid; i < 64*64; i += 256) {
        int r = i >> 6, c = i & 63;
        g_Wcat[(64 + r)*64 + c] = w0[r*128 + 64 + c];
    }
    for (int i = tid; i < 128*64; i += 256) {
        int r = i >> 6, c = i & 63;
        g_Wcat[(128 + r)*64 + c] = scw[r*64 + c];
    }
    for (int i = tid; i < 128*64; i += 256) {
        int r = i >> 6, c = i & 63;
        float w = w1[r*64 + c];
        __half h = __float2half_rn(w);
        __half l = __float2half_rn(w - __half2float(h));
        g_w1h[r*72 + c] = *reinterpret_cast<unsigned short*>(&h);
        g_w1l[r*72 + c] = *reinterpret_cast<unsigned short*>(&l);
    }
    for (int i = tid; i < 128*128; i += 256) {
        int r = i >> 7, c = i & 127;
        float w = w2[r*128 + c];
        __half h = __float2half_rn(w);
        __half l = __float2half_rn(w - __half2float(h));
        g_w2h[r*136 + c] = *reinterpret_cast<unsigned short*>(&h);
        g_w2l[r*136 + c] = *reinterpret_cast<unsigned short*>(&l);
    }
}

// ---------------- kNN ----------------
__global__ void knn_kernel(const float* __restrict__ pts) {
    __shared__ float px[512], py[512];
    int b = blockIdx.x, n = threadIdx.x;
    px[n] = pts[b*1024 + n];
    py[n] = pts[b*1024 + 512 + n];
    __syncthreads();
    float x0 = px[n], y0v = py[n];
    float bd[KNN]; int bi[KNN];
#pragma unroll
    for (int i = 0; i < KNN; i++) { bd[i] = 1e30f; bi[i] = 0; }
    for (int m = 0; m < 512; m++) {
        if (m == n) continue;
        float dx = px[m] - x0, dy = py[m] - y0v;
        float d = fmaf(dx, dx, dy*dy);
        if (d < bd[KNN-1]) {
            int j = KNN - 1;
            while (j > 0 && bd[j-1] > d) { bd[j] = bd[j-1]; bi[j] = bi[j-1]; j--; }
            bd[j] = d; bi[j] = m;
        }
    }
    int base = (b*512 + n)*KNN;
#pragma unroll
    for (int k = 0; k < KNN; k++) g_idx[base + k] = bi[k];
}

// ---------------- gemm_f: PQS[p][r] = sum_c Wcat[r][c] * f[b][c][n] ----------------
__global__ void gemm_f_kernel(const float* __restrict__ f) {
    __shared__ float Wst[64*65];
    __shared__ float fs[64*65];
    int tid = threadIdx.x;
    int rt0 = blockIdx.x*64, n0 = blockIdx.y*64, b = blockIdx.z;
#pragma unroll
    for (int s = 0; s < 16; s++) {
        int idx = tid + 256*s;
        int c = idx & 63, rl = idx >> 6;
        Wst[c*65 + rl] = g_Wcat[(rt0 + rl)*64 + c];
    }
#pragma unroll
    for (int s = 0; s < 16; s++) {
        int idx = tid + 256*s;
        int nl = idx & 63, c = idx >> 6;
        fs[c*65 + nl] = f[b*32768 + c*512 + n0 + nl];
    }
    __syncthreads();
    int tx = tid & 15, ty = tid >> 4;
    float acc[4][4];
#pragma unroll
    for (int i = 0; i < 4; i++)
#pragma unroll
        for (int j = 0; j < 4; j++) acc[i][j] = 0.f;
#pragma unroll 4
    for (int c = 0; c < 64; c++) {
        float fv[4];
#pragma unroll
        for (int j = 0; j < 4; j++) fv[j] = fs[c*65 + ty*4 + j];
#pragma unroll
        for (int i = 0; i < 4; i++) {
            float w = Wst[c*65 + tx + 16*i];
#pragma unroll
            for (int j = 0; j < 4; j++) acc[i][j] = fmaf(w, fv[j], acc[i][j]);
        }
    }
#pragma unroll
    for (int j = 0; j < 4; j++) {
        float* dst = &g_PQS[(size_t)(b*512 + n0 + ty*4 + j)*256 + rt0 + tx];
#pragma unroll
        for (int i = 0; i < 4; i++) dst[16*i] = acc[i][j];
    }
}

// ---------------- stats of y0 = P[n] + Q[idx] ----------------
__global__ void stats0_kernel() {
    __shared__ float red[128];
    int tid = threadIdx.x;
    int c = tid & 63, q = tid >> 6;
    float s = 0.f, s2 = 0.f;
    for (int p = blockIdx.x*4 + q; p < BB*NN; p += SGRID*4) {
        float Pv = g_PQS[(size_t)p*256 + c];
        size_t rowbase = (size_t)(p & ~511)*256;
#pragma unroll
        for (int k = 0; k < KNN; k++) {
            int m = g_idx[p*KNN + k];
            float y = Pv + g_PQS[rowbase + (size_t)m*256 + 64 + c];
            s += y; s2 += y*y;
        }
    }
    if (tid < 128) red[tid] = 0.f;
    __syncthreads();
    atomicAdd(&red[c], s);
    atomicAdd(&red[64 + c], s2);
    __syncthreads();
    if (tid < 128) g_part0[blockIdx.x*128 + tid] = red[tid];
}

// ---------------- stats of shortcut pre-BN ----------------
__global__ void statssc_kernel() {
    __shared__ float red[256];
    int tid = threadIdx.x;
    int c = tid & 127, q = tid >> 7;
    float s = 0.f, s2 = 0.f;
    for (int p = blockIdx.x*2 + q; p < BB*NN; p += SGRID*2) {
        float v = g_PQS[(size_t)p*256 + 128 + c];
        s += v; s2 += v*v;
    }
    red[tid] = 0.f;
    __syncthreads();
    atomicAdd(&red[c], s);
    atomicAdd(&red[128 + c], s2);
    __syncthreads();
    g_partsc[blockIdx.x*256 + tid] = red[tid];
}

// ---------------- finalize ----------------
__global__ void finalize_kernel(const float* __restrict__ part, int nblocks, int nch,
                                const float* __restrict__ g, const float* __restrict__ bt,
                                float minv, float* a_out, float* c_out) {
    int c = threadIdx.x;
    if (c >= nch) return;
    float s = 0.f, s2 = 0.f;
    for (int i = 0; i < nblocks; i++) {
        s  += part[i*2*nch + c];
        s2 += part[i*2*nch + nch + c];
    }
    float mean = s*minv;
    float var = s2*minv - mean*mean;
    float a = g[c] * rsqrtf(var + 1e-5f);
    a_out[c] = a;
    c_out[c] = bt[c] - a*mean;
}

// ---------------- layer1: fp16 mma.sync, W split hi/lo (2 MMA), K=64 ----------------
// smem: Whi[128*72] Wlo[128*72] Xh[64*72] (ushort)
__global__ void __launch_bounds__(256) layer1_kernel() {
    extern __shared__ char smraw[];
    unsigned short* Whi = (unsigned short*)smraw;
    unsigned short* Wlo = Whi + 128*72;
    unsigned short* Xh  = Wlo + 128*72;
    int tid = threadIdx.x;
    int w = tid >> 5, t = tid & 31;

    {
        uint32_t* dh = (uint32_t*)Whi; uint32_t* dl = (uint32_t*)Wlo;
        const uint32_t* s1 = (const uint32_t*)g_w1h;
        const uint32_t* s2 = (const uint32_t*)g_w1l;
        for (int i = tid; i < 4608; i += 256) { dh[i] = s1[i]; dl[i] = s2[i]; }
    }
    __syncthreads();

    int M0 = w*16;
    uint32_t aoff = (uint32_t)(((M0 + (t & 15))*72 + ((t >> 4) & 1)*8)*2);
    uint32_t awh = smem_u32(Whi) + aoff;
    uint32_t awl = smem_u32(Wlo) + aoff;
    uint32_t bx  = smem_u32(Xh) + (uint32_t)((t & 15)*144);

    unsigned ahi[4][4];
#pragma unroll
    for (int k = 0; k < 4; k++) LDSM_X4(ahi[k], awh + k*32);

    int c = tid & 63, eg = tid >> 6;
    float a0v = g_a0[c], c0v = g_c0[c];
    int q = t >> 2;
    float rs0 = 0.f, rq0 = 0.f, rs1 = 0.f, rq1 = 0.f;

    for (int tt = blockIdx.x; tt < NTILES; tt += L1GRID) {
        int e0 = tt*64;
#pragma unroll
        for (int s = 0; s < 8; s++) {
            int eloc = eg*16 + 2*s;
            int e = e0 + eloc;
            int p0 = e >> 4, p1 = (e + 1) >> 4;
            int m0 = g_idx[e], m1 = g_idx[e + 1];
            float Pv0 = g_PQS[(size_t)p0*256 + c];
            float Qv0 = g_PQS[(size_t)((p0 & ~511) + m0)*256 + 64 + c];
            float Pv1 = g_PQS[(size_t)p1*256 + c];
            float Qv1 = g_PQS[(size_t)((p1 & ~511) + m1)*256 + 64 + c];
            float v0 = fmaxf(fmaf(a0v, Pv0 + Qv0, c0v), 0.f);
            float v1 = fmaxf(fmaf(a0v, Pv1 + Qv1, c0v), 0.f);
            *reinterpret_cast<__half2*>(&Xh[c*72 + eloc]) = __floats2half2_rn(v0, v1);
        }
        __syncthreads();
        float acc[8][4];
#pragma unroll
        for (int j = 0; j < 8; j++)
#pragma unroll
            for (int i = 0; i < 4; i++) acc[j][i] = 0.f;
#pragma unroll
        for (int k = 0; k < 4; k++) {
            unsigned alo[4];
            LDSM_X4(alo, awl + k*32);
#pragma unroll
            for (int j = 0; j < 8; j++) {
                unsigned bh[2];
                LDSM_X2T(bh, bx + (uint32_t)(k*2304 + j*16));
                MMA_F16(acc[j], ahi[k], bh);
                MMA_F16(acc[j], alo,    bh);
            }
        }
        __syncthreads();
        int r0 = M0 + q;
        __half* b0p = &g_y1h[((size_t)tt*128 + r0)*64];
        __half* b1p = b0p + 8*64;
#pragma unroll
        for (int j = 0; j < 8; j++) {
            int n = j*8 + ((t & 3) << 1);
            *(__half2*)(b0p + n) = __floats2half2_rn(acc[j][0], acc[j][1]);
            *(__half2*)(b1p + n) = __floats2half2_rn(acc[j][2], acc[j][3]);
            rs0 += acc[j][0] + acc[j][1];
            rq0 += acc[j][0]*acc[j][0] + acc[j][1]*acc[j][1];
            rs1 += acc[j][2] + acc[j][3];
            rq1 += acc[j][2]*acc[j][2] + acc[j][3]*acc[j][3];
        }
    }
    rs0 += __shfl_xor_sync(0xffffffffu, rs0, 1); rs0 += __shfl_xor_sync(0xffffffffu, rs0, 2);
    rq0 += __shfl_xor_sync(0xffffffffu, rq0, 1); rq0 += __shfl_xor_sync(0xffffffffu, rq0, 2);
    rs1 += __shfl_xor_sync(0xffffffffu, rs1, 1); rs1 += __shfl_xor_sync(0xffffffffu, rs1, 2);
    rq1 += __shfl_xor_sync(0xffffffffu, rq1, 1); rq1 += __shfl_xor_sync(0xffffffffu, rq1, 2);
    if ((t & 3) == 0) {
        int r0 = M0 + q;
        g_part1[blockIdx.x*256 + r0]           = rs0;
        g_part1[blockIdx.x*256 + r0 + 8]       = rs1;
        g_part1[blockIdx.x*256 + 128 + r0]     = rq0;
        g_part1[blockIdx.x*256 + 128 + r0 + 8] = rq1;
    }
}

// ---------------- layer2: fp16 mma.sync, W split hi/lo (2 MMA), K=128 ----------------
// smem: Whi[128*136] Wlo[128*136] Xh[128*72]
__global__ void __launch_bounds__(256) layer2_kernel() {
    extern __shared__ char smraw[];
    unsigned short* Whi = (unsigned short*)smraw;
    unsigned short* Wlo = Whi + 128*136;
    unsigned short* Xh  = Wlo + 128*136;
    __shared__ float s_a[128], s_c[128];
    int tid = threadIdx.x;
    int w = tid >> 5, t = tid & 31;

    {
        uint32_t* dh = (uint32_t*)Whi; uint32_t* dl = (uint32_t*)Wlo;
        const uint32_t* s1 = (const uint32_t*)g_w2h;
        const uint32_t* s2 = (const uint32_t*)g_w2l;
        for (int i = tid; i < 8704; i += 256) { dh[i] = s1[i]; dl[i] = s2[i]; }
    }
    if (tid < 128) { s_a[tid] = g_a1[tid]; s_c[tid] = g_c1[tid]; }
    __syncthreads();

    int M0 = w*16;
    uint32_t aoff = (uint32_t)(((M0 + (t & 15))*136 + ((t >> 4) & 1)*8)*2);
    uint32_t awh = smem_u32(Whi) + aoff;
    uint32_t awl = smem_u32(Wlo) + aoff;
    uint32_t bx  = smem_u32(Xh) + (uint32_t)((t & 15)*144);

    unsigned ahi[8][4];
#pragma unroll
    for (int k = 0; k < 8; k++) LDSM_X4(ahi[k], awh + k*32);

    int q = t >> 2;
    float rs0 = 0.f, rq0 = 0.f, rs1 = 0.f, rq1 = 0.f;
    const uint32_t* y1p = (const uint32_t*)g_y1h;

    for (int tt = blockIdx.x; tt < NTILES; tt += L2GRID) {
#pragma unroll
        for (int s = 0; s < 16; s++) {
            int idx = tid + 256*s;            // 0..4095
            int k = idx >> 5, e2 = idx & 31;  // k row, half2 col
            uint32_t hbits = y1p[((size_t)tt*128 + k)*32 + e2];
            __half2 hh = *reinterpret_cast<__half2*>(&hbits);
            float2 f = __half22float2(hh);
            float ak = s_a[k], ck = s_c[k];
            float v0 = fmaxf(fmaf(ak, f.x, ck), 0.f);
            float v1 = fmaxf(fmaf(ak, f.y, ck), 0.f);
            *reinterpret_cast<__half2*>(&Xh[k*72 + 2*e2]) = __floats2half2_rn(v0, v1);
        }
        __syncthreads();
        float acc[8][4];
#pragma unroll
        for (int j = 0; j < 8; j++)
#pragma unroll
            for (int i = 0; i < 4; i++) acc[j][i] = 0.f;
#pragma unroll
        for (int k = 0; k < 8; k++) {
            unsigned alo[4];
            LDSM_X4(alo, awl + k*32);
#pragma unroll
            for (int j = 0; j < 8; j++) {
                unsigned bh[2];
                LDSM_X2T(bh, bx + (uint32_t)(k*2304 + j*16));
                MMA_F16(acc[j], ahi[k], bh);
                MMA_F16(acc[j], alo,    bh);
            }
        }
        __syncthreads();
        int r0 = M0 + q;
        __half* b0p = &g_y2h[((size_t)tt*128 + r0)*64];
        __half* b1p = b0p + 8*64;
#pragma unroll
        for (int j = 0; j < 8; j++) {
            int n = j*8 + ((t & 3) << 1);
            *(__half2*)(b0p + n) = __floats2half2_rn(acc[j][0], acc[j][1]);
            *(__half2*)(b1p + n) = __floats2half2_rn(acc[j][2], acc[j][3]);
            rs0 += acc[j][0] + acc[j][1];
            rq0 += acc[j][0]*acc[j][0] + acc[j][1]*acc[j][1];
            rs1 += acc[j][2] + acc[j][3];
            rq1 += acc[j][2]*acc[j][2] + acc[j][3]*acc[j][3];
        }
    }
    rs0 += __shfl_xor_sync(0xffffffffu, rs0, 1); rs0 += __shfl_xor_sync(0xffffffffu, rs0, 2);
    rq0 += __shfl_xor_sync(0xffffffffu, rq0, 1); rq0 += __shfl_xor_sync(0xffffffffu, rq0, 2);
    rs1 += __shfl_xor_sync(0xffffffffu, rs1, 1); rs1 += __shfl_xor_sync(0xffffffffu, rs1, 2);
    rq1 += __shfl_xor_sync(0xffffffffu, rq1, 1); rq1 += __shfl_xor_sync(0xffffffffu, rq1, 2);
    if ((t & 3) == 0) {
        int r0 = M0 + q;
        g_part2[blockIdx.x*256 + r0]           = rs0;
        g_part2[blockIdx.x*256 + r0 + 8]       = rs1;
        g_part2[blockIdx.x*256 + 128 + r0]     = rq0;
        g_part2[blockIdx.x*256 + 128 + r0 + 8] = rq1;
    }
}

// ---------------- out: fts = mean_k relu(a2*y2+c2); out = relu(asc*sc+csc + fts) ----------------
__global__ void out_kernel(float* __restrict__ out) {
    __shared__ float res[128*33];
    int tid = threadIdx.x;
    int b = blockIdx.x >> 4;
    int n0 = (blockIdx.x & 15)*32;
    int o = tid & 127, ng = tid >> 7;
    float a2v = g_a2[o], c2v = g_c2[o];
    float ascv = g_asc[o], cscv = g_csc[o];
#pragma unroll
    for (int s = 0; s < 16; s++) {
        int nloc = ng + 2*s;
        int p = b*512 + n0 + nloc;
        int t = p >> 2, q = p & 3;
        const __half2* yr = (const __half2*)&g_y2h[((size_t)t*128 + o)*64 + q*16];
        float fts = 0.f;
#pragma unroll
        for (int kk = 0; kk < 8; kk++) {
            float2 f = __half22float2(yr[kk]);
            fts += fmaxf(fmaf(a2v, f.x, c2v), 0.f) + fmaxf(fmaf(a2v, f.y, c2v), 0.f);
        }
        fts *= (1.0f/KNN);
        float sc = fmaf(ascv, g_PQS[(size_t)p*256 + 128 + o], cscv);
        res[o*33 + nloc] = fmaxf(sc + fts, 0.f);
    }
    __syncthreads();
#pragma unroll
    for (int s = 0; s < 16; s++) {
        int idx = tid + 256*s;
        int oo = idx >> 5, nl = idx & 31;
        out[(size_t)(b*128 + oo)*512 + n0 + nl] = res[oo*33 + nl];
    }
}

// ---------------- launch ----------------
extern "C" void kernel_launch(void* const* d_in, const int* in_sizes, int n_in,
                              void* d_out, int out_size) {
    const float* pts  = (const float*)d_in[0];
    const float* feat = (const float*)d_in[1];
    const float* w0   = (const float*)d_in[2];
    const float* g0   = (const float*)d_in[3];
    const float* b0   = (const float*)d_in[4];
    const float* w1   = (const float*)d_in[5];
    const float* g1   = (const float*)d_in[6];
    const float* b1   = (const float*)d_in[7];
    const float* w2   = (const float*)d_in[8];
    const float* g2   = (const float*)d_in[9];
    const float* b2   = (const float*)d_in[10];
    const float* scw  = (const float*)d_in[11];
    const float* scg  = (const float*)d_in[12];
    const float* scb  = (const float*)d_in[13];
    float* out = (float*)d_out;

    const int SMEM1 = (128*72*2 + 64*72)*2;    // 46080
    const int SMEM2 = (128*136*2 + 128*72)*2;  // 88064
    cudaFuncSetAttribute(layer1_kernel, cudaFuncAttributeMaxDynamicSharedMemorySize, SMEM1);
    cudaFuncSetAttribute(layer2_kernel, cudaFuncAttributeMaxDynamicSharedMemorySize, SMEM2);

    float *pa0, *pc0, *pa1, *pc1, *pa2, *pc2, *pasc, *pcsc;
    float *pp0, *ppsc, *pp1, *pp2;
    cudaGetSymbolAddress((void**)&pa0,  g_a0);
    cudaGetSymbolAddress((void**)&pc0,  g_c0);
    cudaGetSymbolAddress((void**)&pa1,  g_a1);
    cudaGetSymbolAddress((void**)&pc1,  g_c1);
    cudaGetSymbolAddress((void**)&pa2,  g_a2);
    cudaGetSymbolAddress((void**)&pc2,  g_c2);
    cudaGetSymbolAddress((void**)&pasc, g_asc);
    cudaGetSymbolAddress((void**)&pcsc, g_csc);
    cudaGetSymbolAddress((void**)&pp0,  g_part0);
    cudaGetSymbolAddress((void**)&ppsc, g_partsc);
    cudaGetSymbolAddress((void**)&pp1,  g_part1);
    cudaGetSymbolAddress((void**)&pp2,  g_part2);

    prep_kernel<<<1, 256>>>(w0, w1, w2, scw);
    knn_kernel<<<BB, 512>>>(pts);
    gemm_f_kernel<<<dim3(4, 8, BB), 256>>>(feat);
    stats0_kernel<<<SGRID, 256>>>();
    statssc_kernel<<<SGRID, 256>>>();
    finalize_kernel<<<1, 64>>>(pp0, SGRID, 64, g0, b0, 1.0f/(float)E_TOT, pa0, pc0);
    finalize_kernel<<<1, 128>>>(ppsc, SGRID, 128, scg, scb, 1.0f/(float)(BB*NN), pasc, pcsc);
    layer1_kernel<<<L1GRID, 256, SMEM1>>>();
    finalize_kernel<<<1, 128>>>(pp1, L1GRID, 128, g1, b1, 1.0f/(float)E_TOT, pa1, pc1);
    layer2_kernel<<<L2GRID, 256, SMEM2>>>();
    finalize_kernel<<<1, 128>>>(pp2, L2GRID, 128, g2, b2, 1.0f/(float)E_TOT, pa2, pc2);
    out_kernel<<<BB*16, 256>>>(out);

    (void)in_sizes; (void)n_in; (void)out_size;
}

// round 14
// speedup vs baseline: 1.4093x; 1.0304x over previous
#include <cuda_runtime.h>
#include <cuda_fp16.h>
#include <math.h>
#include <stdint.h>

#define BB 128
#define NN 512
#define KNN 16
#define E_TOT (BB*NN*KNN)      /* 1048576 edges */
#define NTILES (E_TOT/64)      /* 16384 tiles of 64 edges */
#define L1GRID 592
#define L2GRID 296
#define SGRID 512

// ---------------- helpers ----------------
__device__ __forceinline__ uint32_t smem_u32(const void* p) {
    uint32_t a;
    asm("{ .reg .u64 t; cvta.to.shared.u64 t, %1; cvt.u32.u64 %0, t; }" : "=r"(a) : "l"(p));
    return a;
}
#define LDSM_X4(r, a) \
    asm volatile("ldmatrix.sync.aligned.m8n8.x4.shared.b16 {%0,%1,%2,%3}, [%4];" \
        : "=r"((r)[0]), "=r"((r)[1]), "=r"((r)[2]), "=r"((r)[3]) : "r"(a))
#define LDSM_X4T(r, a) \
    asm volatile("ldmatrix.sync.aligned.m8n8.x4.trans.shared.b16 {%0,%1,%2,%3}, [%4];" \
        : "=r"((r)[0]), "=r"((r)[1]), "=r"((r)[2]), "=r"((r)[3]) : "r"(a))
#define MMA_F16(c, a, b) \
    asm volatile("mma.sync.aligned.m16n8k16.row.col.f32.f16.f16.f32 " \
        "{%0,%1,%2,%3}, {%4,%5,%6,%7}, {%8,%9}, {%0,%1,%2,%3};" \
        : "+f"((c)[0]), "+f"((c)[1]), "+f"((c)[2]), "+f"((c)[3]) \
        : "r"((a)[0]), "r"((a)[1]), "r"((a)[2]), "r"((a)[3]), "r"((b)[0]), "r"((b)[1]))

// ---------------- scratch (static __device__; no allocation) ----------------
__device__ int   g_idx[E_TOT];
__device__ float g_PQS[BB*NN*256];          // [p][0:64)=P, [64:128)=Q, [128:256)=sc pre-BN
__device__ float g_Wcat[256*64];
__device__ __align__(16) unsigned short g_w1h[128*72];    // W1 fp16, row stride 72
__device__ __align__(16) unsigned short g_w2h[128*136];   // W2 fp16, row stride 136
__device__ __half g_y1h[134217728];         // [t][128ch][64e] pre-BN layer1 (fp16)
__device__ __half g_y2h[134217728];         // [t][128ch][64e] pre-BN layer2 (fp16)
__device__ float g_part0[SGRID*128];
__device__ float g_partsc[SGRID*256];
__device__ float g_part1[2048*256];
__device__ float g_part2[2048*256];
__device__ float g_a0[64],  g_c0[64];
__device__ float g_a1[128], g_c1[128];
__device__ float g_a2[128], g_c2[128];
__device__ float g_asc[128], g_csc[128];

// ---------------- prep: fold w0, W1/W2 -> fp16 padded ----------------
__global__ void prep_kernel(const float* __restrict__ w0, const float* __restrict__ w1,
                            const float* __restrict__ w2, const float* __restrict__ scw) {
    int tid = threadIdx.x;
    for (int i = tid; i < 64*64; i += 256) {
        int r = i >> 6, c = i & 63;
        g_Wcat[r*64 + c] = w0[r*128 + c] - w0[r*128 + 64 + c];
    }
    for (int i = tid; i < 64*64; i += 256) {
        int r = i >> 6, c = i & 63;
        g_Wcat[(64 + r)*64 + c] = w0[r*128 + 64 + c];
    }
    for (int i = tid; i < 128*64; i += 256) {
        int r = i >> 6, c = i & 63;
        g_Wcat[(128 + r)*64 + c] = scw[r*64 + c];
    }
    for (int i = tid; i < 128*64; i += 256) {
        int r = i >> 6, c = i & 63;
        __half h = __float2half_rn(w1[r*64 + c]);
        g_w1h[r*72 + c] = *reinterpret_cast<unsigned short*>(&h);
    }
    for (int i = tid; i < 128*128; i += 256) {
        int r = i >> 7, c = i & 127;
        __half h = __float2half_rn(w2[r*128 + c]);
        g_w2h[r*136 + c] = *reinterpret_cast<unsigned short*>(&h);
    }
}

// ---------------- kNN ----------------
__global__ void knn_kernel(const float* __restrict__ pts) {
    __shared__ float px[512], py[512];
    int b = blockIdx.x, n = threadIdx.x;
    px[n] = pts[b*1024 + n];
    py[n] = pts[b*1024 + 512 + n];
    __syncthreads();
    float x0 = px[n], y0v = py[n];
    float bd[KNN]; int bi[KNN];
#pragma unroll
    for (int i = 0; i < KNN; i++) { bd[i] = 1e30f; bi[i] = 0; }
    for (int m = 0; m < 512; m++) {
        if (m == n) continue;
        float dx = px[m] - x0, dy = py[m] - y0v;
        float d = fmaf(dx, dx, dy*dy);
        if (d < bd[KNN-1]) {
            int j = KNN - 1;
            while (j > 0 && bd[j-1] > d) { bd[j] = bd[j-1]; bi[j] = bi[j-1]; j--; }
            bd[j] = d; bi[j] = m;
        }
    }
    int base = (b*512 + n)*KNN;
#pragma unroll
    for (int k = 0; k < KNN; k++) g_idx[base + k] = bi[k];
}

// ---------------- gemm_f: PQS[p][r] = sum_c Wcat[r][c] * f[b][c][n] ----------------
__global__ void gemm_f_kernel(const float* __restrict__ f) {
    __shared__ float Wst[64*65];
    __shared__ float fs[64*65];
    int tid = threadIdx.x;
    int rt0 = blockIdx.x*64, n0 = blockIdx.y*64, b = blockIdx.z;
#pragma unroll
    for (int s = 0; s < 16; s++) {
        int idx = tid + 256*s;
        int c = idx & 63, rl = idx >> 6;
        Wst[c*65 + rl] = g_Wcat[(rt0 + rl)*64 + c];
    }
#pragma unroll
    for (int s = 0; s < 16; s++) {
        int idx = tid + 256*s;
        int nl = idx & 63, c = idx >> 6;
        fs[c*65 + nl] = f[b*32768 + c*512 + n0 + nl];
    }
    __syncthreads();
    int tx = tid & 15, ty = tid >> 4;
    float acc[4][4];
#pragma unroll
    for (int i = 0; i < 4; i++)
#pragma unroll
        for (int j = 0; j < 4; j++) acc[i][j] = 0.f;
#pragma unroll 4
    for (int c = 0; c < 64; c++) {
        float fv[4];
#pragma unroll
        for (int j = 0; j < 4; j++) fv[j] = fs[c*65 + ty*4 + j];
#pragma unroll
        for (int i = 0; i < 4; i++) {
            float w = Wst[c*65 + tx + 16*i];
#pragma unroll
            for (int j = 0; j < 4; j++) acc[i][j] = fmaf(w, fv[j], acc[i][j]);
        }
    }
#pragma unroll
    for (int j = 0; j < 4; j++) {
        float* dst = &g_PQS[(size_t)(b*512 + n0 + ty*4 + j)*256 + rt0 + tx];
#pragma unroll
        for (int i = 0; i < 4; i++) dst[16*i] = acc[i][j];
    }
}

// ---------------- stats of y0 = P[n] + Q[idx] ----------------
__global__ void stats0_kernel() {
    __shared__ float red[128];
    int tid = threadIdx.x;
    int c = tid & 63, q = tid >> 6;
    float s = 0.f, s2 = 0.f;
    for (int p = blockIdx.x*4 + q; p < BB*NN; p += SGRID*4) {
        float Pv = g_PQS[(size_t)p*256 + c];
        size_t rowbase = (size_t)(p & ~511)*256;
#pragma unroll
        for (int k = 0; k < KNN; k++) {
            int m = g_idx[p*KNN + k];
            float y = Pv + g_PQS[rowbase + (size_t)m*256 + 64 + c];
            s += y; s2 += y*y;
        }
    }
    if (tid < 128) red[tid] = 0.f;
    __syncthreads();
    atomicAdd(&red[c], s);
    atomicAdd(&red[64 + c], s2);
    __syncthreads();
    if (tid < 128) g_part0[blockIdx.x*128 + tid] = red[tid];
}

// ---------------- stats of shortcut pre-BN ----------------
__global__ void statssc_kernel() {
    __shared__ float red[256];
    int tid = threadIdx.x;
    int c = tid & 127, q = tid >> 7;
    float s = 0.f, s2 = 0.f;
    for (int p = blockIdx.x*2 + q; p < BB*NN; p += SGRID*2) {
        float v = g_PQS[(size_t)p*256 + 128 + c];
        s += v; s2 += v*v;
    }
    red[tid] = 0.f;
    __syncthreads();
    atomicAdd(&red[c], s);
    atomicAdd(&red[128 + c], s2);
    __syncthreads();
    g_partsc[blockIdx.x*256 + tid] = red[tid];
}

// ---------------- finalize ----------------
__global__ void finalize_kernel(const float* __restrict__ part, int nblocks, int nch,
                                const float* __restrict__ g, const float* __restrict__ bt,
                                float minv, float* a_out, float* c_out) {
    int c = threadIdx.x;
    if (c >= nch) return;
    float s = 0.f, s2 = 0.f;
    for (int i = 0; i < nblocks; i++) {
        s  += part[i*2*nch + c];
        s2 += part[i*2*nch + nch + c];
    }
    float mean = s*minv;
    float var = s2*minv - mean*mean;
    float a = g[c] * rsqrtf(var + 1e-5f);
    a_out[c] = a;
    c_out[c] = bt[c] - a*mean;
}

// ---------------- layer1: fp16 mma.sync (1 MMA), x4.trans B loads, K=64 ----------------
// smem: Whi[128*72] Xh[64*72] (ushort)
__global__ void __launch_bounds__(256) layer1_kernel() {
    extern __shared__ char smraw[];
    unsigned short* Whi = (unsigned short*)smraw;
    unsigned short* Xh  = Whi + 128*72;
    int tid = threadIdx.x;
    int w = tid >> 5, t = tid & 31;

    {
        uint32_t* dh = (uint32_t*)Whi;
        const uint32_t* s1 = (const uint32_t*)g_w1h;
        for (int i = tid; i < 4608; i += 256) dh[i] = s1[i];
    }
    __syncthreads();

    int M0 = w*16;
    uint32_t aoff = (uint32_t)(((M0 + (t & 15))*72 + ((t >> 4) & 1)*8)*2);
    uint32_t awh = smem_u32(Whi) + aoff;
    // B addressing for x4.trans: lanes 0-15 rows k0..15 at col n0; lanes 16-31 same rows at n0+8
    uint32_t bx = smem_u32(Xh) + (uint32_t)((t & 15)*144 + ((t >> 4) & 1)*16);

    unsigned ahi[4][4];
#pragma unroll
    for (int k = 0; k < 4; k++) LDSM_X4(ahi[k], awh + k*32);

    int c = tid & 63, eg = tid >> 6;
    float a0v = g_a0[c], c0v = g_c0[c];
    int q = t >> 2;
    float rs0 = 0.f, rq0 = 0.f, rs1 = 0.f, rq1 = 0.f;

    for (int tt = blockIdx.x; tt < NTILES; tt += L1GRID) {
        int e0 = tt*64;
#pragma unroll
        for (int s = 0; s < 8; s++) {
            int eloc = eg*16 + 2*s;
            int e = e0 + eloc;
            int p0 = e >> 4, p1 = (e + 1) >> 4;
            int m0 = g_idx[e], m1 = g_idx[e + 1];
            float Pv0 = g_PQS[(size_t)p0*256 + c];
            float Qv0 = g_PQS[(size_t)((p0 & ~511) + m0)*256 + 64 + c];
            float Pv1 = g_PQS[(size_t)p1*256 + c];
            float Qv1 = g_PQS[(size_t)((p1 & ~511) + m1)*256 + 64 + c];
            float v0 = fmaxf(fmaf(a0v, Pv0 + Qv0, c0v), 0.f);
            float v1 = fmaxf(fmaf(a0v, Pv1 + Qv1, c0v), 0.f);
            *reinterpret_cast<__half2*>(&Xh[c*72 + eloc]) = __floats2half2_rn(v0, v1);
        }
        __syncthreads();
        float acc[8][4];
#pragma unroll
        for (int j = 0; j < 8; j++)
#pragma unroll
            for (int i = 0; i < 4; i++) acc[j][i] = 0.f;
#pragma unroll
        for (int k = 0; k < 4; k++) {
#pragma unroll
            for (int j = 0; j < 8; j += 2) {
                unsigned b4[4];
                LDSM_X4T(b4, bx + (uint32_t)(k*2304 + j*16));
                MMA_F16(acc[j],     ahi[k], b4);
                MMA_F16(acc[j + 1], ahi[k], b4 + 2);
            }
        }
        __syncthreads();
        int r0 = M0 + q;
        __half* b0p = &g_y1h[((size_t)tt*128 + r0)*64];
        __half* b1p = b0p + 8*64;
#pragma unroll
        for (int j = 0; j < 8; j++) {
            int n = j*8 + ((t & 3) << 1);
            *(__half2*)(b0p + n) = __floats2half2_rn(acc[j][0], acc[j][1]);
            *(__half2*)(b1p + n) = __floats2half2_rn(acc[j][2], acc[j][3]);
            rs0 += acc[j][0] + acc[j][1];
            rq0 += acc[j][0]*acc[j][0] + acc[j][1]*acc[j][1];
            rs1 += acc[j][2] + acc[j][3];
            rq1 += acc[j][2]*acc[j][2] + acc[j][3]*acc[j][3];
        }
    }
    rs0 += __shfl_xor_sync(0xffffffffu, rs0, 1); rs0 += __shfl_xor_sync(0xffffffffu, rs0, 2);
    rq0 += __shfl_xor_sync(0xffffffffu, rq0, 1); rq0 += __shfl_xor_sync(0xffffffffu, rq0, 2);
    rs1 += __shfl_xor_sync(0xffffffffu, rs1, 1); rs1 += __shfl_xor_sync(0xffffffffu, rs1, 2);
    rq1 += __shfl_xor_sync(0xffffffffu, rq1, 1); rq1 += __shfl_xor_sync(0xffffffffu, rq1, 2);
    if ((t & 3) == 0) {
        int r0 = M0 + q;
        g_part1[blockIdx.x*256 + r0]           = rs0;
        g_part1[blockIdx.x*256 + r0 + 8]       = rs1;
        g_part1[blockIdx.x*256 + 128 + r0]     = rq0;
        g_part1[blockIdx.x*256 + 128 + r0 + 8] = rq1;
    }
}

// ---------------- layer2: fp16 mma.sync (1 MMA), x4.trans B loads, K=128 ----------------
// smem: Whi[128*136] Xh[128*72]
__global__ void __launch_bounds__(256) layer2_kernel() {
    extern __shared__ char smraw[];
    unsigned short* Whi = (unsigned short*)smraw;
    unsigned short* Xh  = Whi + 128*136;
    __shared__ float s_a[128], s_c[128];
    int tid = threadIdx.x;
    int w = tid >> 5, t = tid & 31;

    {
        uint32_t* dh = (uint32_t*)Whi;
        const uint32_t* s1 = (const uint32_t*)g_w2h;
        for (int i = tid; i < 8704; i += 256) dh[i] = s1[i];
    }
    if (tid < 128) { s_a[tid] = g_a1[tid]; s_c[tid] = g_c1[tid]; }
    __syncthreads();

    int M0 = w*16;
    uint32_t aoff = (uint32_t)(((M0 + (t & 15))*136 + ((t >> 4) & 1)*8)*2);
    uint32_t awh = smem_u32(Whi) + aoff;
    uint32_t bx = smem_u32(Xh) + (uint32_t)((t & 15)*144 + ((t >> 4) & 1)*16);

    unsigned ahi[8][4];
#pragma unroll
    for (int k = 0; k < 8; k++) LDSM_X4(ahi[k], awh + k*32);

    int q = t >> 2;
    float rs0 = 0.f, rq0 = 0.f, rs1 = 0.f, rq1 = 0.f;
    const uint32_t* y1p = (const uint32_t*)g_y1h;

    for (int tt = blockIdx.x; tt < NTILES; tt += L2GRID) {
#pragma unroll
        for (int s = 0; s < 16; s++) {
            int idx = tid + 256*s;            // 0..4095
            int k = idx >> 5, e2 = idx & 31;  // k row, half2 col
            uint32_t hbits = y1p[((size_t)tt*128 + k)*32 + e2];
            __half2 hh = *reinterpret_cast<__half2*>(&hbits);
            float2 f = __half22float2(hh);
            float ak = s_a[k], ck = s_c[k];
            float v0 = fmaxf(fmaf(ak, f.x, ck), 0.f);
            float v1 = fmaxf(fmaf(ak, f.y, ck), 0.f);
            *reinterpret_cast<__half2*>(&Xh[k*72 + 2*e2]) = __floats2half2_rn(v0, v1);
        }
        __syncthreads();
        float acc[8][4];
#pragma unroll
        for (int j = 0; j < 8; j++)
#pragma unroll
            for (int i = 0; i < 4; i++) acc[j][i] = 0.f;
#pragma unroll
        for (int k = 0; k < 8; k++) {
#pragma unroll
            for (int j = 0; j < 8; j += 2) {
                unsigned b4[4];
                LDSM_X4T(b4, bx + (uint32_t)(k*2304 + j*16));
                MMA_F16(acc[j],     ahi[k], b4);
                MMA_F16(acc[j + 1], ahi[k], b4 + 2);
            }
        }
        __syncthreads();
        int r0 = M0 + q;
        __half* b0p = &g_y2h[((size_t)tt*128 + r0)*64];
        __half* b1p = b0p + 8*64;
#pragma unroll
        for (int j = 0; j < 8; j++) {
            int n = j*8 + ((t & 3) << 1);
            *(__half2*)(b0p + n) = __floats2half2_rn(acc[j][0], acc[j][1]);
            *(__half2*)(b1p + n) = __floats2half2_rn(acc[j][2], acc[j][3]);
            rs0 += acc[j][0] + acc[j][1];
            rq0 += acc[j][0]*acc[j][0] + acc[j][1]*acc[j][1];
            rs1 += acc[j][2] + acc[j][3];
            rq1 += acc[j][2]*acc[j][2] + acc[j][3]*acc[j][3];
        }
    }
    rs0 += __shfl_xor_sync(0xffffffffu, rs0, 1); rs0 += __shfl_xor_sync(0xffffffffu, rs0, 2);
    rq0 += __shfl_xor_sync(0xffffffffu, rq0, 1); rq0 += __shfl_xor_sync(0xffffffffu, rq0, 2);
    rs1 += __shfl_xor_sync(0xffffffffu, rs1, 1); rs1 += __shfl_xor_sync(0xffffffffu, rs1, 2);
    rq1 += __shfl_xor_sync(0xffffffffu, rq1, 1); rq1 += __shfl_xor_sync(0xffffffffu, rq1, 2);
    if ((t & 3) == 0) {
        int r0 = M0 + q;
        g_part2[blockIdx.x*256 + r0]           = rs0;
        g_part2[blockIdx.x*256 + r0 + 8]       = rs1;
        g_part2[blockIdx.x*256 + 128 + r0]     = rq0;
        g_part2[blockIdx.x*256 + 128 + r0 + 8] = rq1;
    }
}

// ---------------- out: fts = mean_k relu(a2*y2+c2); out = relu(asc*sc+csc + fts) ----------------
__global__ void out_kernel(float* __restrict__ out) {
    __shared__ float res[128*33];
    int tid = threadIdx.x;
    int b = blockIdx.x >> 4;
    int n0 = (blockIdx.x & 15)*32;
    int o = tid & 127, ng = tid >> 7;
    float a2v = g_a2[o], c2v = g_c2[o];
    float ascv = g_asc[o], cscv = g_csc[o];
#pragma unroll
    for (int s = 0; s < 16; s++) {
        int nloc = ng + 2*s;
        int p = b*512 + n0 + nloc;
        int t = p >> 2, q = p & 3;
        const __half2* yr = (const __half2*)&g_y2h[((size_t)t*128 + o)*64 + q*16];
        float fts = 0.f;
#pragma unroll
        for (int kk = 0; kk < 8; kk++) {
            float2 f = __half22float2(yr[kk]);
            fts += fmaxf(fmaf(a2v, f.x, c2v), 0.f) + fmaxf(fmaf(a2v, f.y, c2v), 0.f);
        }
        fts *= (1.0f/KNN);
        float sc = fmaf(ascv, g_PQS[(size_t)p*256 + 128 + o], cscv);
        res[o*33 + nloc] = fmaxf(sc + fts, 0.f);
    }
    __syncthreads();
#pragma unroll
    for (int s = 0; s < 16; s++) {
        int idx = tid + 256*s;
        int oo = idx >> 5, nl = idx & 31;
        out[(size_t)(b*128 + oo)*512 + n0 + nl] = res[oo*33 + nl];
    }
}

// ---------------- launch ----------------
extern "C" void kernel_launch(void* const* d_in, const int* in_sizes, int n_in,
                              void* d_out, int out_size) {
    const float* pts  = (const float*)d_in[0];
    const float* feat = (const float*)d_in[1];
    const float* w0   = (const float*)d_in[2];
    const float* g0   = (const float*)d_in[3];
    const float* b0   = (const float*)d_in[4];
    const float* w1   = (const float*)d_in[5];
    const float* g1   = (const float*)d_in[6];
    const float* b1   = (const float*)d_in[7];
    const float* w2   = (const float*)d_in[8];
    const float* g2   = (const float*)d_in[9];
    const float* b2   = (const float*)d_in[10];
    const float* scw  = (const float*)d_in[11];
    const float* scg  = (const float*)d_in[12];
    const float* scb  = (const float*)d_in[13];
    float* out = (float*)d_out;

    const int SMEM1 = (128*72 + 64*72)*2;    // 27648
    const int SMEM2 = (128*136 + 128*72)*2;  // 53248
    cudaFuncSetAttribute(layer1_kernel, cudaFuncAttributeMaxDynamicSharedMemorySize, SMEM1);
    cudaFuncSetAttribute(layer2_kernel, cudaFuncAttributeMaxDynamicSharedMemorySize, SMEM2);

    float *pa0, *pc0, *pa1, *pc1, *pa2, *pc2, *pasc, *pcsc;
    float *pp0, *ppsc, *pp1, *pp2;
    cudaGetSymbolAddress((void**)&pa0,  g_a0);
    cudaGetSymbolAddress((void**)&pc0,  g_c0);
    cudaGetSymbolAddress((void**)&pa1,  g_a1);
    cudaGetSymbolAddress((void**)&pc1,  g_c1);
    cudaGetSymbolAddress((void**)&pa2,  g_a2);
    cudaGetSymbolAddress((void**)&pc2,  g_c2);
    cudaGetSymbolAddress((void**)&pasc, g_asc);
    cudaGetSymbolAddress((void**)&pcsc, g_csc);
    cudaGetSymbolAddress((void**)&pp0,  g_part0);
    cudaGetSymbolAddress((void**)&ppsc, g_partsc);
    cudaGetSymbolAddress((void**)&pp1,  g_part1);
    cudaGetSymbolAddress((void**)&pp2,  g_part2);

    prep_kernel<<<1, 256>>>(w0, w1, w2, scw);
    knn_kernel<<<BB, 512>>>(pts);
    gemm_f_kernel<<<dim3(4, 8, BB), 256>>>(feat);
    stats0_kernel<<<SGRID, 256>>>();
    statssc_kernel<<<SGRID, 256>>>();
    finalize_kernel<<<1, 64>>>(pp0, SGRID, 64, g0, b0, 1.0f/(float)E_TOT, pa0, pc0);
    finalize_kernel<<<1, 128>>>(ppsc, SGRID, 128, scg, scb, 1.0f/(float)(BB*NN), pasc, pcsc);
    layer1_kernel<<<L1GRID, 256, SMEM1>>>();
    finalize_kernel<<<1, 128>>>(pp1, L1GRID, 128, g1, b1, 1.0f/(float)E_TOT, pa1, pc1);
    layer2_kernel<<<L2GRID, 256, SMEM2>>>();
    finalize_kernel<<<1, 128>>>(pp2, L2GRID, 128, g2, b2, 1.0f/(float)E_TOT, pa2, pc2);
    out_kernel<<<BB*16, 256>>>(out);

    (void)in_sizes; (void)n_in; (void)out_size;
}

// round 16
// speedup vs baseline: 1.8250x; 1.2950x over previous
#include <cuda_runtime.h>
#include <cuda_fp16.h>
#include <math.h>
#include <stdint.h>

#define BB 128
#define NN 512
#define KNN 16
#define E_TOT (BB*NN*KNN)      /* 1048576 edges */
#define NTILES (E_TOT/64)      /* 16384 tiles of 64 edges */
#define L1GRID 592
#define L2GRID 296
#define SGRID 512

// ---------------- helpers ----------------
__device__ __forceinline__ uint32_t smem_u32(const void* p) {
    uint32_t a;
    asm("{ .reg .u64 t; cvta.to.shared.u64 t, %1; cvt.u32.u64 %0, t; }" : "=r"(a) : "l"(p));
    return a;
}
__device__ __forceinline__ void sts_h2(uint32_t saddr, __half2 v) {
    asm volatile("st.shared.b32 [%0], %1;" :: "r"(saddr), "r"(*reinterpret_cast<unsigned*>(&v)));
}
#define LDSM_X4(r, a) \
    asm volatile("ldmatrix.sync.aligned.m8n8.x4.shared.b16 {%0,%1,%2,%3}, [%4];" \
        : "=r"((r)[0]), "=r"((r)[1]), "=r"((r)[2]), "=r"((r)[3]) : "r"(a))
#define LDSM_X4T(r, a) \
    asm volatile("ldmatrix.sync.aligned.m8n8.x4.trans.shared.b16 {%0,%1,%2,%3}, [%4];" \
        : "=r"((r)[0]), "=r"((r)[1]), "=r"((r)[2]), "=r"((r)[3]) : "r"(a))
#define MMA_F16(c, a, b) \
    asm volatile("mma.sync.aligned.m16n8k16.row.col.f32.f16.f16.f32 " \
        "{%0,%1,%2,%3}, {%4,%5,%6,%7}, {%8,%9}, {%0,%1,%2,%3};" \
        : "+f"((c)[0]), "+f"((c)[1]), "+f"((c)[2]), "+f"((c)[3]) \
        : "r"((a)[0]), "r"((a)[1]), "r"((a)[2]), "r"((a)[3]), "r"((b)[0]), "r"((b)[1]))

// ---------------- scratch (static __device__; no allocation) ----------------
__device__ int   g_idx[E_TOT];
__device__ float g_PQS[BB*NN*256];          // [p][0:64)=P, [64:128)=Q, [128:256)=sc pre-BN
__device__ float g_Wcat[256*64];
__device__ __align__(16) unsigned short g_wcth[256*72], g_wctl[256*72];  // Wcat fp16 hi/lo
__device__ __align__(16) unsigned short g_w1h[128*72];    // W1 fp16, row stride 72
__device__ __align__(16) unsigned short g_w2h[128*136];   // W2 fp16, row stride 136
__device__ __half g_y1h[134217728];         // [t][128ch][64e] pre-BN layer1 (fp16)
__device__ __half g_y2h[134217728];         // [t][128ch][64e] pre-BN layer2 (fp16)
__device__ float g_part0[SGRID*128];
__device__ float g_partsc[SGRID*256];
__device__ float g_part1[2048*256];
__device__ float g_part2[2048*256];
__device__ float g_a0[64],  g_c0[64];
__device__ float g_a1[128], g_c1[128];
__device__ float g_a2[128], g_c2[128];
__device__ float g_asc[128], g_csc[128];

// ---------------- prep: fold w0, fp16 conversions ----------------
__global__ void prep_kernel(const float* __restrict__ w0, const float* __restrict__ w1,
                            const float* __restrict__ w2, const float* __restrict__ scw) {
    int tid = threadIdx.x;
    for (int i = tid; i < 64*64; i += 256) {
        int r = i >> 6, c = i & 63;
        g_Wcat[r*64 + c] = w0[r*128 + c] - w0[r*128 + 64 + c];
    }
    for (int i = tid; i < 64*64; i += 256) {
        int r = i >> 6, c = i & 63;
        g_Wcat[(64 + r)*64 + c] = w0[r*128 + 64 + c];
    }
    for (int i = tid; i < 128*64; i += 256) {
        int r = i >> 6, c = i & 63;
        g_Wcat[(128 + r)*64 + c] = scw[r*64 + c];
    }
    __syncthreads();
    for (int i = tid; i < 256*64; i += 256) {
        int r = i >> 6, c = i & 63;
        float w = g_Wcat[r*64 + c];
        __half h = __float2half_rn(w);
        __half l = __float2half_rn(w - __half2float(h));
        g_wcth[r*72 + c] = *reinterpret_cast<unsigned short*>(&h);
        g_wctl[r*72 + c] = *reinterpret_cast<unsigned short*>(&l);
    }
    for (int i = tid; i < 128*64; i += 256) {
        int r = i >> 6, c = i & 63;
        __half h = __float2half_rn(w1[r*64 + c]);
        g_w1h[r*72 + c] = *reinterpret_cast<unsigned short*>(&h);
    }
    for (int i = tid; i < 128*128; i += 256) {
        int r = i >> 7, c = i & 127;
        __half h = __float2half_rn(w2[r*128 + c]);
        g_w2h[r*136 + c] = *reinterpret_cast<unsigned short*>(&h);
    }
}

// ---------------- kNN ----------------
__global__ void knn_kernel(const float* __restrict__ pts) {
    __shared__ float px[512], py[512];
    int b = blockIdx.x, n = threadIdx.x;
    px[n] = pts[b*1024 + n];
    py[n] = pts[b*1024 + 512 + n];
    __syncthreads();
    float x0 = px[n], y0v = py[n];
    float bd[KNN]; int bi[KNN];
#pragma unroll
    for (int i = 0; i < KNN; i++) { bd[i] = 1e30f; bi[i] = 0; }
    for (int m = 0; m < 512; m++) {
        if (m == n) continue;
        float dx = px[m] - x0, dy = py[m] - y0v;
        float d = fmaf(dx, dx, dy*dy);
        if (d < bd[KNN-1]) {
            int j = KNN - 1;
            while (j > 0 && bd[j-1] > d) { bd[j] = bd[j-1]; bi[j] = bi[j-1]; j--; }
            bd[j] = d; bi[j] = m;
        }
    }
    int base = (b*512 + n)*KNN;
#pragma unroll
    for (int k = 0; k < KNN; k++) g_idx[base + k] = bi[k];
}

// ---------------- gemm_f: fp16 MMA (3-term hi/lo split), PQS = Wcat * f ----------------
__global__ void __launch_bounds__(256) gemm_f_kernel(const float* __restrict__ f) {
    extern __shared__ char smraw[];
    unsigned short* Wh = (unsigned short*)smraw;     // 128*72
    unsigned short* Wl = Wh + 128*72;
    unsigned short* Xh = Wl + 128*72;                // 64*72
    unsigned short* Xl = Xh + 64*72;
    int tid = threadIdx.x;
    int w = tid >> 5, t = tid & 31;
    int hh = blockIdx.y;
    int b = blockIdx.x >> 3, nt = blockIdx.x & 7;
    int n0 = nt*64;

    {
        const uint32_t* sh = (const uint32_t*)(g_wcth + hh*128*72);
        const uint32_t* sl = (const uint32_t*)(g_wctl + hh*128*72);
        uint32_t* dh = (uint32_t*)Wh; uint32_t* dl = (uint32_t*)Wl;
        for (int i = tid; i < 4608; i += 256) { dh[i] = sh[i]; dl[i] = sl[i]; }
    }
#pragma unroll
    for (int s = 0; s < 8; s++) {
        int idx = tid + 256*s;
        int cc = idx >> 5, n2 = idx & 31;
        float2 vv = *(const float2*)&f[b*32768 + cc*512 + n0 + 2*n2];
        __half hx = __float2half_rn(vv.x), hy = __float2half_rn(vv.y);
        float lx = vv.x - __half2float(hx), ly = vv.y - __half2float(hy);
        *reinterpret_cast<__half2*>(&Xh[cc*72 + 2*n2]) = __halves2half2(hx, hy);
        *reinterpret_cast<__half2*>(&Xl[cc*72 + 2*n2]) = __floats2half2_rn(lx, ly);
    }
    __syncthreads();

    int M0 = w*16;
    uint32_t aoff = (uint32_t)(((M0 + (t & 15))*72 + ((t >> 4) & 1)*8)*2);
    uint32_t awh = smem_u32(Wh) + aoff;
    uint32_t awl = smem_u32(Wl) + aoff;
    uint32_t bxh = smem_u32(Xh) + (uint32_t)((t & 15)*144 + ((t >> 4) & 1)*16);
    uint32_t bxl = smem_u32(Xl) + (uint32_t)((t & 15)*144 + ((t >> 4) & 1)*16);

    unsigned ahi[4][4], alo[4][4];
#pragma unroll
    for (int k = 0; k < 4; k++) { LDSM_X4(ahi[k], awh + k*32); LDSM_X4(alo[k], awl + k*32); }

    float acc[8][4];
#pragma unroll
    for (int j = 0; j < 8; j++)
#pragma unroll
        for (int i = 0; i < 4; i++) acc[j][i] = 0.f;
#pragma unroll
    for (int k = 0; k < 4; k++) {
#pragma unroll
        for (int j = 0; j < 8; j += 2) {
            unsigned bh4[4], bl4[4];
            LDSM_X4T(bh4, bxh + (uint32_t)(k*2304 + j*16));
            LDSM_X4T(bl4, bxl + (uint32_t)(k*2304 + j*16));
            MMA_F16(acc[j],     ahi[k], bh4);
            MMA_F16(acc[j + 1], ahi[k], bh4 + 2);
            MMA_F16(acc[j],     alo[k], bh4);
            MMA_F16(acc[j + 1], alo[k], bh4 + 2);
            MMA_F16(acc[j],     ahi[k], bl4);
            MMA_F16(acc[j + 1], ahi[k], bl4 + 2);
        }
    }
    int q = t >> 2;
    int r_lo = hh*128 + M0 + q;
#pragma unroll
    for (int j = 0; j < 8; j++) {
        int n = n0 + j*8 + ((t & 3) << 1);
        size_t p0 = (size_t)(b*512 + n)*256;
        g_PQS[p0 + r_lo]           = acc[j][0];
        g_PQS[p0 + 256 + r_lo]     = acc[j][1];
        g_PQS[p0 + r_lo + 8]       = acc[j][2];
        g_PQS[p0 + 256 + r_lo + 8] = acc[j][3];
    }
}

// ---------------- stats of y0 = P[n] + Q[idx] ----------------
__global__ void stats0_kernel() {
    __shared__ float red[128];
    int tid = threadIdx.x;
    int c = tid & 63, q = tid >> 6;
    float s = 0.f, s2 = 0.f;
    for (int p = blockIdx.x*4 + q; p < BB*NN; p += SGRID*4) {
        float Pv = g_PQS[(size_t)p*256 + c];
        size_t rowbase = (size_t)(p & ~511)*256;
#pragma unroll
        for (int k = 0; k < KNN; k++) {
            int m = g_idx[p*KNN + k];
            float y = Pv + g_PQS[rowbase + (size_t)m*256 + 64 + c];
            s += y; s2 += y*y;
        }
    }
    if (tid < 128) red[tid] = 0.f;
    __syncthreads();
    atomicAdd(&red[c], s);
    atomicAdd(&red[64 + c], s2);
    __syncthreads();
    if (tid < 128) g_part0[blockIdx.x*128 + tid] = red[tid];
}

// ---------------- stats of shortcut pre-BN ----------------
__global__ void statssc_kernel() {
    __shared__ float red[256];
    int tid = threadIdx.x;
    int c = tid & 127, q = tid >> 7;
    float s = 0.f, s2 = 0.f;
    for (int p = blockIdx.x*2 + q; p < BB*NN; p += SGRID*2) {
        float v = g_PQS[(size_t)p*256 + 128 + c];
        s += v; s2 += v*v;
    }
    red[tid] = 0.f;
    __syncthreads();
    atomicAdd(&red[c], s);
    atomicAdd(&red[128 + c], s2);
    __syncthreads();
    g_partsc[blockIdx.x*256 + tid] = red[tid];
}

// ---------------- finalize ----------------
__global__ void finalize_kernel(const float* __restrict__ part, int nblocks, int nch,
                                const float* __restrict__ g, const float* __restrict__ bt,
                                float minv, float* a_out, float* c_out) {
    int c = threadIdx.x;
    if (c >= nch) return;
    float s = 0.f, s2 = 0.f;
    for (int i = 0; i < nblocks; i++) {
        s  += part[i*2*nch + c];
        s2 += part[i*2*nch + nch + c];
    }
    float mean = s*minv;
    float var = s2*minv - mean*mean;
    float a = g[c] * rsqrtf(var + 1e-5f);
    a_out[c] = a;
    c_out[c] = bt[c] - a*mean;
}

// ---------------- layer1: fp16 mma, double-buffered X, 1 sync/tile ----------------
__global__ void __launch_bounds__(256) layer1_kernel() {
    extern __shared__ char smraw[];
    unsigned short* Whi = (unsigned short*)smraw;   // 128*72
    unsigned short* Xh  = Whi + 128*72;             // 2 x 64*72
    int tid = threadIdx.x;
    int w = tid >> 5, t = tid & 31;

    {
        uint32_t* dh = (uint32_t*)Whi;
        const uint32_t* s1 = (const uint32_t*)g_w1h;
        for (int i = tid; i < 4608; i += 256) dh[i] = s1[i];
    }
    __syncthreads();

    int M0 = w*16;
    uint32_t aoff = (uint32_t)(((M0 + (t & 15))*72 + ((t >> 4) & 1)*8)*2);
    uint32_t awh = smem_u32(Whi) + aoff;
    uint32_t bxb = smem_u32(Xh) + (uint32_t)((t & 15)*144 + ((t >> 4) & 1)*16);

    unsigned ahi[4][4];
#pragma unroll
    for (int k = 0; k < 4; k++) LDSM_X4(ahi[k], awh + k*32);

    int c = tid & 63, eg = tid >> 6;
    float a0v = g_a0[c], c0v = g_c0[c];
    uint32_t xsts = smem_u32(Xh) + (uint32_t)(c*144);
    int q = t >> 2;
    float rs0 = 0.f, rq0 = 0.f, rs1 = 0.f, rq1 = 0.f;

    int tt = blockIdx.x;
    int4 mi4[4]; float pv; float qv[16];
    {
        const int4* ip = (const int4*)&g_idx[tt*64 + eg*16];
#pragma unroll
        for (int s = 0; s < 4; s++) mi4[s] = ip[s];
        int p = tt*4 + eg;
        pv = g_PQS[(size_t)p*256 + c];
        const int* mi = (const int*)mi4;
        size_t rowbase = (size_t)(p & ~511)*256 + 64 + c;
#pragma unroll
        for (int s = 0; s < 16; s++) qv[s] = g_PQS[rowbase + (size_t)mi[s]*256];
    }

    int par = 0;
    for (; tt < NTILES; tt += L1GRID) {
        uint32_t xs = xsts + (uint32_t)par*9216u;
#pragma unroll
        for (int s = 0; s < 8; s++) {
            float v0 = fmaxf(fmaf(a0v, pv + qv[2*s],     c0v), 0.f);
            float v1 = fmaxf(fmaf(a0v, pv + qv[2*s + 1], c0v), 0.f);
            sts_h2(xs + (uint32_t)(eg*16 + 2*s)*2u, __floats2half2_rn(v0, v1));
        }
        __syncthreads();
        int tn = tt + L1GRID;
        int pnext = 0;
        if (tn < NTILES) {
            const int4* ip = (const int4*)&g_idx[tn*64 + eg*16];
#pragma unroll
            for (int s = 0; s < 4; s++) mi4[s] = ip[s];
            pnext = tn*4 + eg;
            pv = g_PQS[(size_t)pnext*256 + c];
        }
        float acc[8][4];
#pragma unroll
        for (int j = 0; j < 8; j++)
#pragma unroll
            for (int i = 0; i < 4; i++) acc[j][i] = 0.f;
        uint32_t bx = bxb + (uint32_t)par*9216u;
#pragma unroll
        for (int k = 0; k < 4; k++) {
#pragma unroll
            for (int j = 0; j < 8; j += 2) {
                unsigned b4[4];
                LDSM_X4T(b4, bx + (uint32_t)(k*2304 + j*16));
                MMA_F16(acc[j],     ahi[k], b4);
                MMA_F16(acc[j + 1], ahi[k], b4 + 2);
            }
        }
        if (tn < NTILES) {
            const int* mi = (const int*)mi4;
            size_t rowbase = (size_t)(pnext & ~511)*256 + 64 + c;
#pragma unroll
            for (int s = 0; s < 16; s++) qv[s] = g_PQS[rowbase + (size_t)mi[s]*256];
        }
        int r0 = M0 + q;
        __half* b0p = &g_y1h[((size_t)tt*128 + r0)*64];
        __half* b1p = b0p + 8*64;
#pragma unroll
        for (int j = 0; j < 8; j++) {
            int n = j*8 + ((t & 3) << 1);
            *(__half2*)(b0p + n) = __floats2half2_rn(acc[j][0], acc[j][1]);
            *(__half2*)(b1p + n) = __floats2half2_rn(acc[j][2], acc[j][3]);
            rs0 += acc[j][0] + acc[j][1];
            rq0 += acc[j][0]*acc[j][0] + acc[j][1]*acc[j][1];
            rs1 += acc[j][2] + acc[j][3];
            rq1 += acc[j][2]*acc[j][2] + acc[j][3]*acc[j][3];
        }
        par ^= 1;
    }
    rs0 += __shfl_xor_sync(0xffffffffu, rs0, 1); rs0 += __shfl_xor_sync(0xffffffffu, rs0, 2);
    rq0 += __shfl_xor_sync(0xffffffffu, rq0, 1); rq0 += __shfl_xor_sync(0xffffffffu, rq0, 2);
    rs1 += __shfl_xor_sync(0xffffffffu, rs1, 1); rs1 += __shfl_xor_sync(0xffffffffu, rs1, 2);
    rq1 += __shfl_xor_sync(0xffffffffu, rq1, 1); rq1 += __shfl_xor_sync(0xffffffffu, rq1, 2);
    if ((t & 3) == 0) {
        int r0 = M0 + q;
        g_part1[blockIdx.x*256 + r0]           = rs0;
        g_part1[blockIdx.x*256 + r0 + 8]       = rs1;
        g_part1[blockIdx.x*256 + 128 + r0]     = rq0;
        g_part1[blockIdx.x*256 + 128 + r0 + 8] = rq1;
    }
}

// ---------------- layer2: fp16 mma, double-buffered X, 1 sync/tile, K=128 ----------------
__global__ void __launch_bounds__(256) layer2_kernel() {
    extern __shared__ char smraw[];
    unsigned short* Whi = (unsigned short*)smraw;   // 128*136
    unsigned short* Xh  = Whi + 128*136;            // 2 x 128*72
    __shared__ float s_a[128], s_c[128];
    int tid = threadIdx.x;
    int w = tid >> 5, t = tid & 31;

    {
        uint32_t* dh = (uint32_t*)Whi;
        const uint32_t* s1 = (const uint32_t*)g_w2h;
        for (int i = tid; i < 8704; i += 256) dh[i] = s1[i];
    }
    if (tid < 128) { s_a[tid] = g_a1[tid]; s_c[tid] = g_c1[tid]; }
    __syncthreads();

    int M0 = w*16;
    uint32_t aoff = (uint32_t)(((M0 + (t & 15))*136 + ((t >> 4) & 1)*8)*2);
    uint32_t awh = smem_u32(Whi) + aoff;
    uint32_t bxb = smem_u32(Xh) + (uint32_t)((t & 15)*144 + ((t >> 4) & 1)*16);

    unsigned ahi[8][4];
#pragma unroll
    for (int k = 0; k < 8; k++) LDSM_X4(ahi[k], awh + k*32);

    int k0 = tid >> 5, e2 = tid & 31;
    int q = t >> 2;
    float rs0 = 0.f, rq0 = 0.f, rs1 = 0.f, rq1 = 0.f;
    const uint32_t* y1p = (const uint32_t*)g_y1h;

    int tt = blockIdx.x;
    uint32_t h[16];
#pragma unroll
    for (int s = 0; s < 16; s++)
        h[s] = y1p[((size_t)tt*128 + k0 + 8*s)*32 + e2];

    int par = 0;
    for (; tt < NTILES; tt += L2GRID) {
        uint32_t xs = smem_u32(Xh) + (uint32_t)par*18432u;
#pragma unroll
        for (int s = 0; s < 16; s++) {
            int k = k0 + 8*s;
            __half2 hh = *reinterpret_cast<__half2*>(&h[s]);
            float2 f = __half22float2(hh);
            float ak = s_a[k], ck = s_c[k];
            float v0 = fmaxf(fmaf(ak, f.x, ck), 0.f);
            float v1 = fmaxf(fmaf(ak, f.y, ck), 0.f);
            sts_h2(xs + (uint32_t)(k*144 + 4*e2), __floats2half2_rn(v0, v1));
        }
        __syncthreads();
        int tn = tt + L2GRID;
        if (tn < NTILES) {
#pragma unroll
            for (int s = 0; s < 16; s++)
                h[s] = y1p[((size_t)tn*128 + k0 + 8*s)*32 + e2];
        }
        float acc[8][4];
#pragma unroll
        for (int j = 0; j < 8; j++)
#pragma unroll
            for (int i = 0; i < 4; i++) acc[j][i] = 0.f;
        uint32_t bx = bxb + (uint32_t)par*18432u;
#pragma unroll
        for (int k = 0; k < 8; k++) {
#pragma unroll
            for (int j = 0; j < 8; j += 2) {
                unsigned b4[4];
                LDSM_X4T(b4, bx + (uint32_t)(k*2304 + j*16));
                MMA_F16(acc[j],     ahi[k], b4);
                MMA_F16(acc[j + 1], ahi[k], b4 + 2);
            }
        }
        int r0 = M0 + q;
        __half* b0p = &g_y2h[((size_t)tt*128 + r0)*64];
        __half* b1p = b0p + 8*64;
#pragma unroll
        for (int j = 0; j < 8; j++) {
            int n = j*8 + ((t & 3) << 1);
            *(__half2*)(b0p + n) = __floats2half2_rn(acc[j][0], acc[j][1]);
            *(__half2*)(b1p + n) = __floats2half2_rn(acc[j][2], acc[j][3]);
            rs0 += acc[j][0] + acc[j][1];
            rq0 += acc[j][0]*acc[j][0] + acc[j][1]*acc[j][1];
            rs1 += acc[j][2] + acc[j][3];
            rq1 += acc[j][2]*acc[j][2] + acc[j][3]*acc[j][3];
        }
        par ^= 1;
    }
    rs0 += __shfl_xor_sync(0xffffffffu, rs0, 1); rs0 += __shfl_xor_sync(0xffffffffu, rs0, 2);
    rq0 += __shfl_xor_sync(0xffffffffu, rq0, 1); rq0 += __shfl_xor_sync(0xffffffffu, rq0, 2);
    rs1 += __shfl_xor_sync(0xffffffffu, rs1, 1); rs1 += __shfl_xor_sync(0xffffffffu, rs1, 2);
    rq1 += __shfl_xor_sync(0xffffffffu, rq1, 1); rq1 += __shfl_xor_sync(0xffffffffu, rq1, 2);
    if ((t & 3) == 0) {
        int r0 = M0 + q;
        g_part2[blockIdx.x*256 + r0]           = rs0;
        g_part2[blockIdx.x*256 + r0 + 8]       = rs1;
        g_part2[blockIdx.x*256 + 128 + r0]     = rq0;
        g_part2[blockIdx.x*256 + 128 + r0 + 8] = rq1;
    }
}

// ---------------- out: fts = mean_k relu(a2*y2+c2); out = relu(asc*sc+csc + fts) ----------------
__global__ void out_kernel(float* __restrict__ out) {
    __shared__ float res[128*33];
    int tid = threadIdx.x;
    int b = blockIdx.x >> 4;
    int n0 = (blockIdx.x & 15)*32;
    int o = tid & 127, ng = tid >> 7;
    float a2v = g_a2[o], c2v = g_c2[o];
    float ascv = g_asc[o], cscv = g_csc[o];
#pragma unroll
    for (int s = 0; s < 16; s++) {
        int nloc = ng + 2*s;
        int p = b*512 + n0 + nloc;
        int t = p >> 2, q = p & 3;
        const __half2* yr = (const __half2*)&g_y2h[((size_t)t*128 + o)*64 + q*16];
        float fts = 0.f;
#pragma unroll
        for (int kk = 0; kk < 8; kk++) {
            float2 f = __half22float2(yr[kk]);
            fts += fmaxf(fmaf(a2v, f.x, c2v), 0.f) + fmaxf(fmaf(a2v, f.y, c2v), 0.f);
        }
        fts *= (1.0f/KNN);
        float sc = fmaf(ascv, g_PQS[(size_t)p*256 + 128 + o], cscv);
        res[o*33 + nloc] = fmaxf(sc + fts, 0.f);
    }
    __syncthreads();
#pragma unroll
    for (int s = 0; s < 16; s++) {
        int idx = tid + 256*s;
        int oo = idx >> 5, nl = idx & 31;
        out[(size_t)(b*128 + oo)*512 + n0 + nl] = res[oo*33 + nl];
    }
}

// ---------------- launch ----------------
extern "C" void kernel_launch(void* const* d_in, const int* in_sizes, int n_in,
                              void* d_out, int out_size) {
    const float* pts  = (const float*)d_in[0];
    const float* feat = (const float*)d_in[1];
    const float* w0   = (const float*)d_in[2];
    const float* g0   = (const float*)d_in[3];
    const float* b0   = (const float*)d_in[4];
    const float* w1   = (const float*)d_in[5];
    const float* g1   = (const float*)d_in[6];
    const float* b1   = (const float*)d_in[7];
    const float* w2   = (const float*)d_in[8];
    const float* g2   = (const float*)d_in[9];
    const float* b2   = (const float*)d_in[10];
    const float* scw  = (const float*)d_in[11];
    const float* scg  = (const float*)d_in[12];
    const float* scb  = (const float*)d_in[13];
    float* out = (float*)d_out;

    const int SMEMF = (128*72*2 + 64*72*2)*2;        // 55296
    const int SMEM1 = (128*72 + 2*64*72)*2;          // 36864
    const int SMEM2 = (128*136 + 2*128*72)*2;        // 71680
    cudaFuncSetAttribute(gemm_f_kernel, cudaFuncAttributeMaxDynamicSharedMemorySize, SMEMF);
    cudaFuncSetAttribute(layer1_kernel, cudaFuncAttributeMaxDynamicSharedMemorySize, SMEM1);
    cudaFuncSetAttribute(layer2_kernel, cudaFuncAttributeMaxDynamicSharedMemorySize, SMEM2);

    float *pa0, *pc0, *pa1, *pc1, *pa2, *pc2, *pasc, *pcsc;
    float *pp0, *ppsc, *pp1, *pp2;
    cudaGetSymbolAddress((void**)&pa0,  g_a0);
    cudaGetSymbolAddress((void**)&pc0,  g_c0);
    cudaGetSymbolAddress((void**)&pa1,  g_a1);
    cudaGetSymbolAddress((void**)&pc1,  g_c1);
    cudaGetSymbolAddress((void**)&pa2,  g_a2);
    cudaGetSymbolAddress((void**)&pc2,  g_c2);
    cudaGetSymbolAddress((void**)&pasc, g_asc);
    cudaGetSymbolAddress((void**)&pcsc, g_csc);
    cudaGetSymbolAddress((void**)&pp0,  g_part0);
    cudaGetSymbolAddress((void**)&ppsc, g_partsc);
    cudaGetSymbolAddress((void**)&pp1,  g_part1);
    cudaGetSymbolAddress((void**)&pp2,  g_part2);

    prep_kernel<<<1, 256>>>(w0, w1, w2, scw);
    knn_kernel<<<BB, 512>>>(pts);
    gemm_f_kernel<<<dim3(1024, 2), 256, SMEMF>>>(feat);
    stats0_kernel<<<SGRID, 256>>>();
    statssc_kernel<<<SGRID, 256>>>();
    finalize_kernel<<<1, 64>>>(pp0, SGRID, 64, g0, b0, 1.0f/(float)E_TOT, pa0, pc0);
    finalize_kernel<<<1, 128>>>(ppsc, SGRID, 128, scg, scb, 1.0f/(float)(BB*NN), pasc, pcsc);
    layer1_kernel<<<L1GRID, 256, SMEM1>>>();
    finalize_kernel<<<1, 128>>>(pp1, L1GRID, 128, g1, b1, 1.0f/(float)E_TOT, pa1, pc1);
    layer2_kernel<<<L2GRID, 256, SMEM2>>>();
    finalize_kernel<<<1, 128>>>(pp2, L2GRID, 128, g2, b2, 1.0f/(float)E_TOT, pa2, pc2);
    out_kernel<<<BB*16, 256>>>(out);

    (void)in_sizes; (void)n_in; (void)out_size;
}